// round 6
// baseline (speedup 1.0000x reference)
#include <cuda_runtime.h>
#include <math.h>
#include <stdint.h>

#define B_DIM 32
#define T_SEQ 512
#define D_DIM 512
#define U_DIM 512
#define NG    2048                 // 4*U
#define M_TOT (B_DIM * T_SEQ)     // 16384

// ---------------- scratch (static device memory; no allocations) ----------------
__device__ float g_xg[2][B_DIM][T_SEQ][NG];        // input projections, both dirs (256 MB)
__device__ float g_hbuf[2][2][B_DIM][U_DIM];       // h double buffers (k-PERMUTED, tf32-rounded)
__device__ float g_hb_out[B_DIM][T_SEQ][U_DIM];    // backward-direction outputs
__device__ volatile unsigned g_flags[2][64];       // per-CTA step flags (monotonic across replays)

#define NCTA_DIR    64
#define REC_THREADS 256

// ---------------- tf32 helpers ----------------
__device__ __forceinline__ unsigned f2tf32(float f)
{
    unsigned r;
    asm("cvt.rna.tf32.f32 %0, %1;" : "=r"(r) : "f"(f));
    return r;
}

// D += A@B, m16n8k8, A row-major, B col-major, tf32 in / fp32 accum
__device__ __forceinline__ void mma8(float* c,
                                     unsigned a0, unsigned a1, unsigned a2, unsigned a3,
                                     unsigned b0, unsigned b1)
{
    asm("mma.sync.aligned.m16n8k8.row.col.f32.tf32.tf32.f32 "
        "{%0,%1,%2,%3},{%4,%5,%6,%7},{%8,%9},{%0,%1,%2,%3};"
        : "+f"(c[0]), "+f"(c[1]), "+f"(c[2]), "+f"(c[3])
        : "r"(a0), "r"(a1), "r"(a2), "r"(a3), "r"(b0), "r"(b1));
}

// k-permutation within each 8-block: (pi(k),pi(k)+1) consecutive = (k, k+4)
__device__ __forceinline__ int perm8(int k)
{
    return (k & ~7) | ((k & 3) << 1) | ((k & 7) >> 2);
}

// ---------------- fast transcendentals (MUFU-based, saturation-safe) ----------------
__device__ __forceinline__ float fsigm(float x)
{
    return __fdividef(1.0f, 1.0f + __expf(-x));        // x->+inf: 1, x->-inf: 0
}
__device__ __forceinline__ float ftanh(float x)
{
    return 1.0f - __fdividef(2.0f, 1.0f + __expf(2.0f * x));  // saturates to +-1
}

// =================================================================================
// Kernel A: xg[dir] = x @ W[dir] + b[dir]  — tf32 tensor-core GEMM
// 128x128 block tile, BK=16, 256 threads (8 warps, warp tile 64x32).
// Double-buffered smem; 2 CTAs/SM via launch bounds for latency hiding.
// =================================================================================
#define GS 136
__global__ __launch_bounds__(256, 2) void gemm_xg(
    const float* __restrict__ X,
    const float* __restrict__ Wf, const float* __restrict__ bf,
    const float* __restrict__ Wb, const float* __restrict__ bb)
{
    const int dir = blockIdx.z;
    const float* __restrict__ W    = dir ? Wb : Wf;
    const float* __restrict__ bias = dir ? bb : bf;

    __shared__ float As[2][16][GS];   // [buf][k][m]
    __shared__ float Bs[2][16][GS];   // [buf][k][n]

    const int tid   = threadIdx.x;
    const int mBase = blockIdx.x * 128;
    const int nBase = blockIdx.y * 128;
    const int lane  = tid & 31, wid = tid >> 5;
    const int gid   = lane >> 2, tig = lane & 3;
    const int m0w   = (wid & 1) * 64;
    const int n0w   = (wid >> 1) * 32;

    const int aM  = tid >> 1;            // 0..127
    const int aK0 = (tid & 1) * 8;       // 0 or 8
    const int bK  = tid >> 4;            // 0..15
    const int bN0 = (tid & 15) * 8;      // 0..120

    const float* aP = X + (size_t)(mBase + aM) * D_DIM + aK0;
    const float* bP = W + (size_t)bK * NG + nBase + bN0;

    float4 a0r = *(const float4*)aP;
    float4 a1r = *(const float4*)(aP + 4);
    float4 b0r = *(const float4*)bP;
    float4 b1r = *(const float4*)(bP + 4);

    float acc[4][4][4];
    #pragma unroll
    for (int i = 0; i < 4; i++)
        #pragma unroll
        for (int j = 0; j < 4; j++)
            #pragma unroll
            for (int q = 0; q < 4; q++) acc[i][j][q] = 0.0f;

    // prologue: fill buffer 0
    As[0][aK0 + 0][aM] = __uint_as_float(f2tf32(a0r.x));
    As[0][aK0 + 1][aM] = __uint_as_float(f2tf32(a0r.y));
    As[0][aK0 + 2][aM] = __uint_as_float(f2tf32(a0r.z));
    As[0][aK0 + 3][aM] = __uint_as_float(f2tf32(a0r.w));
    As[0][aK0 + 4][aM] = __uint_as_float(f2tf32(a1r.x));
    As[0][aK0 + 5][aM] = __uint_as_float(f2tf32(a1r.y));
    As[0][aK0 + 6][aM] = __uint_as_float(f2tf32(a1r.z));
    As[0][aK0 + 7][aM] = __uint_as_float(f2tf32(a1r.w));
    {
        float4 c0 = make_float4(__uint_as_float(f2tf32(b0r.x)), __uint_as_float(f2tf32(b0r.y)),
                                __uint_as_float(f2tf32(b0r.z)), __uint_as_float(f2tf32(b0r.w)));
        float4 c1 = make_float4(__uint_as_float(f2tf32(b1r.x)), __uint_as_float(f2tf32(b1r.y)),
                                __uint_as_float(f2tf32(b1r.z)), __uint_as_float(f2tf32(b1r.w)));
        *(float4*)&Bs[0][bK][bN0 + 0] = c0;
        *(float4*)&Bs[0][bK][bN0 + 4] = c1;
    }
    __syncthreads();

    int cur = 0;
    for (int kt = 0; kt < D_DIM; kt += 16) {
        const bool more = (kt + 16 < D_DIM);
        if (more) {
            a0r = *(const float4*)(aP + kt + 16);
            a1r = *(const float4*)(aP + kt + 20);
            b0r = *(const float4*)(bP + (size_t)(kt + 16) * NG);
            b1r = *(const float4*)(bP + (size_t)(kt + 16) * NG + 4);
        }

        #pragma unroll
        for (int kk = 0; kk < 16; kk += 8) {
            unsigned af[4][4], bfr[4][2];
            #pragma unroll
            for (int mf = 0; mf < 4; mf++) {
                int mr = m0w + mf * 16 + gid;
                af[mf][0] = __float_as_uint(As[cur][kk + tig][mr]);
                af[mf][1] = __float_as_uint(As[cur][kk + tig][mr + 8]);
                af[mf][2] = __float_as_uint(As[cur][kk + tig + 4][mr]);
                af[mf][3] = __float_as_uint(As[cur][kk + tig + 4][mr + 8]);
            }
            #pragma unroll
            for (int nf = 0; nf < 4; nf++) {
                int nr = n0w + nf * 8 + gid;
                bfr[nf][0] = __float_as_uint(Bs[cur][kk + tig][nr]);
                bfr[nf][1] = __float_as_uint(Bs[cur][kk + tig + 4][nr]);
            }
            #pragma unroll
            for (int mf = 0; mf < 4; mf++)
                #pragma unroll
                for (int nf = 0; nf < 4; nf++)
                    mma8(acc[mf][nf], af[mf][0], af[mf][1], af[mf][2], af[mf][3],
                         bfr[nf][0], bfr[nf][1]);
        }

        if (more) {
            int nxt = cur ^ 1;
            As[nxt][aK0 + 0][aM] = __uint_as_float(f2tf32(a0r.x));
            As[nxt][aK0 + 1][aM] = __uint_as_float(f2tf32(a0r.y));
            As[nxt][aK0 + 2][aM] = __uint_as_float(f2tf32(a0r.z));
            As[nxt][aK0 + 3][aM] = __uint_as_float(f2tf32(a0r.w));
            As[nxt][aK0 + 4][aM] = __uint_as_float(f2tf32(a1r.x));
            As[nxt][aK0 + 5][aM] = __uint_as_float(f2tf32(a1r.y));
            As[nxt][aK0 + 6][aM] = __uint_as_float(f2tf32(a1r.z));
            As[nxt][aK0 + 7][aM] = __uint_as_float(f2tf32(a1r.w));
            float4 c0 = make_float4(__uint_as_float(f2tf32(b0r.x)), __uint_as_float(f2tf32(b0r.y)),
                                    __uint_as_float(f2tf32(b0r.z)), __uint_as_float(f2tf32(b0r.w)));
            float4 c1 = make_float4(__uint_as_float(f2tf32(b1r.x)), __uint_as_float(f2tf32(b1r.y)),
                                    __uint_as_float(f2tf32(b1r.z)), __uint_as_float(f2tf32(b1r.w)));
            *(float4*)&Bs[nxt][bK][bN0 + 0] = c0;
            *(float4*)&Bs[nxt][bK][bN0 + 4] = c1;
            __syncthreads();
            cur = nxt;
        }
    }

    float* outp = &g_xg[dir][0][0][0];
    #pragma unroll
    for (int nf = 0; nf < 4; nf++) {
        int ncol = nBase + n0w + nf * 8 + 2 * tig;
        float2 bv = *(const float2*)&bias[ncol];
        #pragma unroll
        for (int mf = 0; mf < 4; mf++) {
            int r0 = mBase + m0w + mf * 16 + gid;
            float2 v0 = make_float2(acc[mf][nf][0] + bv.x, acc[mf][nf][1] + bv.y);
            float2 v1 = make_float2(acc[mf][nf][2] + bv.x, acc[mf][nf][3] + bv.y);
            *(float2*)(outp + (size_t)r0 * NG + ncol)       = v0;
            *(float2*)(outp + (size_t)(r0 + 8) * NG + ncol) = v1;
        }
    }
}

// =================================================================================
// Kernel B: persistent bidirectional LSTM recurrence — tf32 tensor cores.
// 128 CTAs (64/dir), 256 threads (8 warps). CTA owns 8 units (= 32 gate-cols).
// Split-K pipelined mma (warps 0-3: K<256, warps 4-7: K>=256) with cp.async.cg.
// Sync: distributed flag barrier — NO atomics. Each CTA stores its step to its
// own flag; threads 0..63 each poll one flag. Removes LTS atomic serialization
// (~27 cyc x 64 arrivals) and the epoch-indirection round trip.
// =================================================================================
#define US_STR 520
#define GP_STR 34
#define SMEM_REC ((2 * 32 * US_STR + 2 * 32 * GP_STR) * 4)

__global__ __launch_bounds__(REC_THREADS, 1) void lstm_rec(
    const float* __restrict__ z,
    const float* __restrict__ Uf, const float* __restrict__ Ub,
    float* __restrict__ out)
{
    extern __shared__ float sm[];
    float* Us = sm;                       // [32 local cols][US_STR] (k-permuted tf32)
    float* hs = sm + 32 * US_STR;         // [32 batches][US_STR]   (k-permuted tf32)
    float* gp = sm + 64 * US_STR;         // [2 khalf][32 batches][GP_STR] partial preacts

    const int bid = blockIdx.x;
    const int dir = bid & 1;
    const int blk = bid >> 1;             // 0..63
    const int u0  = blk * 8;
    const int tid = threadIdx.x;
    const int lane = tid & 31, wid = tid >> 5;
    const int gid = lane >> 2, tig = lane & 3;
    const int mhalf = wid & 1;
    const int gpair = (wid >> 1) & 1;
    const int khalf = wid >> 2;           // threads 0-127: 0, 128-255: 1
    const int g0 = gpair * 2, g1 = g0 + 1;
    const int r0 = mhalf * 16 + gid;
    const int lt = tid & 127;             // index within K-half group
    const float* __restrict__ Uw = dir ? Ub : Uf;

    // flag base (flags are monotonic across graph replays; all equal at entry)
    const unsigned fbase = g_flags[dir][tid & 63];

    // ---- load U slice into smem: Us[localcol][perm8(k)] (tf32), 256 threads ----
    {
        int ci = tid & 31;                // local col: gate(ci>>3) x unit(ci&7)
        int kc = tid >> 5;                // k chunk (0..7), 64 k each
        int g  = ci >> 3, uul = ci & 7;
        const float* src = Uw + (size_t)(g * U_DIM + u0 + uul);
        float* dst = Us + ci * US_STR;
        for (int k = kc * 64; k < kc * 64 + 64; k++)
            dst[perm8(k)] = __uint_as_float(f2tf32(src[(size_t)k * NG]));
    }

    // ---- init state: h0 = c0 = z; h stored k-PERMUTED + tf32-rounded ----
    float cst;
    {
        int b = tid >> 3, uu = tid & 7;
        float zv = z[b * U_DIM + u0 + uu];
        cst = zv;
        g_hbuf[dir][0][b][u0 + ((uu & 3) << 1) + (uu >> 2)] = __uint_as_float(f2tf32(zv));
    }
    __syncthreads();
    if (tid == 0) {
        __threadfence();
        g_flags[dir][blk] = fbase + 1u;   // h0 published
    }

    const float* hrow0 = hs + r0 * US_STR;
    const float* hrow1 = hs + (r0 + 8) * US_STR;
    const float* urow0 = Us + (g0 * 8 + gid) * US_STR;
    const float* urow1 = Us + (g1 * 8 + gid) * US_STR;
    float* gpb = gp + khalf * 32 * GP_STR;
    const float* xgbase = &g_xg[dir][0][0][0];
    const unsigned hs_s = (unsigned)__cvta_generic_to_shared(hs);
    const int eb = tid >> 3, euu = tid & 7;           // epilogue (batch, unit)

    for (int s = 0; s < T_SEQ; s++) {
        const int buf = s & 1;
        const int tt  = dir ? (T_SEQ - 1 - s) : s;

        // prefetch xg for this step (independent of barrier; hides under spin)
        float xr[4];
        {
            const float* xp = xgbase + ((size_t)eb * T_SEQ + tt) * NG + u0 + euu;
            xr[0] = xp[0];
            xr[1] = xp[U_DIM];
            xr[2] = xp[2 * U_DIM];
            xr[3] = xp[3 * U_DIM];
        }

        // wait for all 64 producer CTAs to have published h(s): poll 1 flag/thread
        if (tid < 64) {
            const unsigned need = 1u + (unsigned)s;
            while (g_flags[dir][tid] - fbase < need) { }
        }
        __syncthreads();

        // stage this K-half of h into smem: 2 sub-chunks of 128 k, cp.async.cg 16B
        const float* hsrcBase = &g_hbuf[dir][buf][0][0];
        #pragma unroll
        for (int q = 0; q < 2; q++) {
            const int kq = khalf * 256 + q * 128;
            #pragma unroll
            for (int j = 0; j < 8; j++) {
                int idx = j * 128 + lt;           // 0..1023
                int b   = idx >> 5;
                int k   = kq + (idx & 31) * 4;
                const float* src = hsrcBase + b * U_DIM + k;
                unsigned dst = hs_s + (unsigned)(b * US_STR + k) * 4u;
                asm volatile("cp.async.cg.shared.global [%0], [%1], 16;" :: "r"(dst), "l"(src));
            }
            asm volatile("cp.async.commit_group;");
        }

        float c0f[4] = {0, 0, 0, 0}, c1f[4] = {0, 0, 0, 0};

        // sub-chunk 0 ready -> mma kb 0..15 of this half
        asm volatile("cp.async.wait_group 1;");
        asm volatile("bar.sync %0, 128;" :: "r"(1 + khalf));
        #pragma unroll 4
        for (int kb = 0; kb < 16; kb++) {
            int o = khalf * 256 + kb * 8 + 2 * tig;
            uint2 ar0 = *(const uint2*)(hrow0 + o);
            uint2 ar1 = *(const uint2*)(hrow1 + o);
            uint2 bu0 = *(const uint2*)(urow0 + o);
            uint2 bu1 = *(const uint2*)(urow1 + o);
            mma8(c0f, ar0.x, ar1.x, ar0.y, ar1.y, bu0.x, bu0.y);
            mma8(c1f, ar0.x, ar1.x, ar0.y, ar1.y, bu1.x, bu1.y);
        }
        // sub-chunk 1 ready -> mma kb 16..31
        asm volatile("cp.async.wait_group 0;");
        asm volatile("bar.sync %0, 128;" :: "r"(1 + khalf));
        #pragma unroll 4
        for (int kb = 16; kb < 32; kb++) {
            int o = khalf * 256 + kb * 8 + 2 * tig;
            uint2 ar0 = *(const uint2*)(hrow0 + o);
            uint2 ar1 = *(const uint2*)(hrow1 + o);
            uint2 bu0 = *(const uint2*)(urow0 + o);
            uint2 bu1 = *(const uint2*)(urow1 + o);
            mma8(c0f, ar0.x, ar1.x, ar0.y, ar1.y, bu0.x, bu0.y);
            mma8(c1f, ar0.x, ar1.x, ar0.y, ar1.y, bu1.x, bu1.y);
        }

        // publish partial preactivations
        *(float2*)&gpb[r0 * GP_STR + g0 * 8 + 2 * tig]       = make_float2(c0f[0], c0f[1]);
        *(float2*)&gpb[(r0 + 8) * GP_STR + g0 * 8 + 2 * tig] = make_float2(c0f[2], c0f[3]);
        *(float2*)&gpb[r0 * GP_STR + g1 * 8 + 2 * tig]       = make_float2(c1f[0], c1f[1]);
        *(float2*)&gpb[(r0 + 8) * GP_STR + g1 * 8 + 2 * tig] = make_float2(c1f[2], c1f[3]);
        __syncthreads();

        // epilogue: reduce K-halves + xg, gates (i,f,c,o), state update, stores
        {
            const float* p0 = gp + eb * GP_STR;
            const float* p1 = gp + (32 + eb) * GP_STR;
            float iv = fsigm(xr[0] + p0[euu]       + p1[euu]);
            float fv = fsigm(xr[1] + p0[8 + euu]   + p1[8 + euu]);
            float cc = ftanh(xr[2] + p0[16 + euu]  + p1[16 + euu]);
            float ov = fsigm(xr[3] + p0[24 + euu]  + p1[24 + euu]);
            cst = fv * cst + iv * cc;
            float hv = ov * ftanh(cst);
            g_hbuf[dir][buf ^ 1][eb][u0 + ((euu & 3) << 1) + (euu >> 2)] =
                __uint_as_float(f2tf32(hv));
            if (dir == 0)
                out[((size_t)eb * T_SEQ + s) * U_DIM + u0 + euu] = hv;
            else
                g_hb_out[eb][tt][u0 + euu] = hv;
        }
        __syncthreads();

        // arrive: publish h(s+1) with a plain flag store (no atomics)
        if (tid == 0) {
            __threadfence();
            g_flags[dir][blk] = fbase + 2u + (unsigned)s;
        }
    }
}

// =================================================================================
// Kernel C: out += backward outputs
// =================================================================================
__global__ void add_bwd(float* __restrict__ out)
{
    int i = blockIdx.x * blockDim.x + threadIdx.x;
    const int n4 = B_DIM * T_SEQ * U_DIM / 4;
    if (i < n4) {
        float4 a = ((float4*)out)[i];
        float4 b = ((const float4*)&g_hb_out[0][0][0])[i];
        a.x += b.x; a.y += b.y; a.z += b.z; a.w += b.w;
        ((float4*)out)[i] = a;
    }
}

// =================================================================================
extern "C" void kernel_launch(void* const* d_in, const int* in_sizes, int n_in,
                              void* d_out, int out_size)
{
    const float* x  = (const float*)d_in[0];
    const float* z  = (const float*)d_in[1];
    const float* Wf = (const float*)d_in[2];
    const float* Uf = (const float*)d_in[3];
    const float* bf = (const float*)d_in[4];
    const float* Wb = (const float*)d_in[5];
    const float* Ub = (const float*)d_in[6];
    const float* bb = (const float*)d_in[7];
    float* out = (float*)d_out;

    cudaFuncSetAttribute(lstm_rec, cudaFuncAttributeMaxDynamicSharedMemorySize, SMEM_REC);

    dim3 gg(M_TOT / 128, NG / 128, 2);
    gemm_xg<<<gg, 256>>>(x, Wf, bf, Wb, bb);
    lstm_rec<<<2 * NCTA_DIR, REC_THREADS, SMEM_REC>>>(z, Uf, Ub, out);
    add_bwd<<<(B_DIM * T_SEQ * U_DIM / 4 + 255) / 256, 256>>>(out);
}

// round 7
// speedup vs baseline: 1.0487x; 1.0487x over previous
#include <cuda_runtime.h>
#include <math.h>
#include <stdint.h>

#define B_DIM 32
#define T_SEQ 512
#define D_DIM 512
#define U_DIM 512
#define NG    2048                 // 4*U
#define M_TOT (B_DIM * T_SEQ)     // 16384

// ---------------- scratch (static device memory; no allocations) ----------------
__device__ float g_xg[2][B_DIM][T_SEQ][NG];        // input projections, both dirs (256 MB)
__device__ float g_hbuf[2][2][B_DIM][U_DIM];       // h double buffers (k-PERMUTED, tf32-rounded)
__device__ float g_hb_out[B_DIM][T_SEQ][U_DIM];    // backward-direction outputs
__device__ volatile unsigned g_epoch[2];           // per-direction barrier epoch
__device__ unsigned g_count[2];                    // per-direction arrival counter

#define NCTA_DIR    32
#define REC_THREADS 256
#define UPC         16                             // units per CTA

// ---------------- tf32 helpers ----------------
__device__ __forceinline__ unsigned f2tf32(float f)
{
    unsigned r;
    asm("cvt.rna.tf32.f32 %0, %1;" : "=r"(r) : "f"(f));
    return r;
}

// D += A@B, m16n8k8, A row-major, B col-major, tf32 in / fp32 accum
__device__ __forceinline__ void mma8(float* c,
                                     unsigned a0, unsigned a1, unsigned a2, unsigned a3,
                                     unsigned b0, unsigned b1)
{
    asm("mma.sync.aligned.m16n8k8.row.col.f32.tf32.tf32.f32 "
        "{%0,%1,%2,%3},{%4,%5,%6,%7},{%8,%9},{%0,%1,%2,%3};"
        : "+f"(c[0]), "+f"(c[1]), "+f"(c[2]), "+f"(c[3])
        : "r"(a0), "r"(a1), "r"(a2), "r"(a3), "r"(b0), "r"(b1));
}

// k-permutation within each 8-block: (pi(k),pi(k)+1) consecutive = (k, k+4)
__device__ __forceinline__ int perm8(int k)
{
    return (k & ~7) | ((k & 3) << 1) | ((k & 7) >> 2);
}

// ---------------- fast transcendentals (MUFU-based, saturation-safe) ----------------
__device__ __forceinline__ float fsigm(float x)
{
    return __fdividef(1.0f, 1.0f + __expf(-x));        // x->+inf: 1, x->-inf: 0
}
__device__ __forceinline__ float ftanh(float x)
{
    return 1.0f - __fdividef(2.0f, 1.0f + __expf(2.0f * x));  // saturates to +-1
}

// =================================================================================
// Kernel A: xg[dir] = x @ W[dir] + b[dir]  — tf32 tensor-core GEMM
// 128x128 block tile, BK=16, 256 threads (8 warps, warp tile 64x32).
// Double-buffered smem; 2 CTAs/SM via launch bounds for latency hiding.
// =================================================================================
#define GS 136
__global__ __launch_bounds__(256, 2) void gemm_xg(
    const float* __restrict__ X,
    const float* __restrict__ Wf, const float* __restrict__ bf,
    const float* __restrict__ Wb, const float* __restrict__ bb)
{
    const int dir = blockIdx.z;
    const float* __restrict__ W    = dir ? Wb : Wf;
    const float* __restrict__ bias = dir ? bb : bf;

    __shared__ float As[2][16][GS];   // [buf][k][m]
    __shared__ float Bs[2][16][GS];   // [buf][k][n]

    const int tid   = threadIdx.x;
    const int mBase = blockIdx.x * 128;
    const int nBase = blockIdx.y * 128;
    const int lane  = tid & 31, wid = tid >> 5;
    const int gid   = lane >> 2, tig = lane & 3;
    const int m0w   = (wid & 1) * 64;
    const int n0w   = (wid >> 1) * 32;

    const int aM  = tid >> 1;            // 0..127
    const int aK0 = (tid & 1) * 8;       // 0 or 8
    const int bK  = tid >> 4;            // 0..15
    const int bN0 = (tid & 15) * 8;      // 0..120

    const float* aP = X + (size_t)(mBase + aM) * D_DIM + aK0;
    const float* bP = W + (size_t)bK * NG + nBase + bN0;

    float4 a0r = *(const float4*)aP;
    float4 a1r = *(const float4*)(aP + 4);
    float4 b0r = *(const float4*)bP;
    float4 b1r = *(const float4*)(bP + 4);

    float acc[4][4][4];
    #pragma unroll
    for (int i = 0; i < 4; i++)
        #pragma unroll
        for (int j = 0; j < 4; j++)
            #pragma unroll
            for (int q = 0; q < 4; q++) acc[i][j][q] = 0.0f;

    // prologue: fill buffer 0
    As[0][aK0 + 0][aM] = __uint_as_float(f2tf32(a0r.x));
    As[0][aK0 + 1][aM] = __uint_as_float(f2tf32(a0r.y));
    As[0][aK0 + 2][aM] = __uint_as_float(f2tf32(a0r.z));
    As[0][aK0 + 3][aM] = __uint_as_float(f2tf32(a0r.w));
    As[0][aK0 + 4][aM] = __uint_as_float(f2tf32(a1r.x));
    As[0][aK0 + 5][aM] = __uint_as_float(f2tf32(a1r.y));
    As[0][aK0 + 6][aM] = __uint_as_float(f2tf32(a1r.z));
    As[0][aK0 + 7][aM] = __uint_as_float(f2tf32(a1r.w));
    {
        float4 c0 = make_float4(__uint_as_float(f2tf32(b0r.x)), __uint_as_float(f2tf32(b0r.y)),
                                __uint_as_float(f2tf32(b0r.z)), __uint_as_float(f2tf32(b0r.w)));
        float4 c1 = make_float4(__uint_as_float(f2tf32(b1r.x)), __uint_as_float(f2tf32(b1r.y)),
                                __uint_as_float(f2tf32(b1r.z)), __uint_as_float(f2tf32(b1r.w)));
        *(float4*)&Bs[0][bK][bN0 + 0] = c0;
        *(float4*)&Bs[0][bK][bN0 + 4] = c1;
    }
    __syncthreads();

    int cur = 0;
    for (int kt = 0; kt < D_DIM; kt += 16) {
        const bool more = (kt + 16 < D_DIM);
        if (more) {
            a0r = *(const float4*)(aP + kt + 16);
            a1r = *(const float4*)(aP + kt + 20);
            b0r = *(const float4*)(bP + (size_t)(kt + 16) * NG);
            b1r = *(const float4*)(bP + (size_t)(kt + 16) * NG + 4);
        }

        #pragma unroll
        for (int kk = 0; kk < 16; kk += 8) {
            unsigned af[4][4], bfr[4][2];
            #pragma unroll
            for (int mf = 0; mf < 4; mf++) {
                int mr = m0w + mf * 16 + gid;
                af[mf][0] = __float_as_uint(As[cur][kk + tig][mr]);
                af[mf][1] = __float_as_uint(As[cur][kk + tig][mr + 8]);
                af[mf][2] = __float_as_uint(As[cur][kk + tig + 4][mr]);
                af[mf][3] = __float_as_uint(As[cur][kk + tig + 4][mr + 8]);
            }
            #pragma unroll
            for (int nf = 0; nf < 4; nf++) {
                int nr = n0w + nf * 8 + gid;
                bfr[nf][0] = __float_as_uint(Bs[cur][kk + tig][nr]);
                bfr[nf][1] = __float_as_uint(Bs[cur][kk + tig + 4][nr]);
            }
            #pragma unroll
            for (int mf = 0; mf < 4; mf++)
                #pragma unroll
                for (int nf = 0; nf < 4; nf++)
                    mma8(acc[mf][nf], af[mf][0], af[mf][1], af[mf][2], af[mf][3],
                         bfr[nf][0], bfr[nf][1]);
        }

        if (more) {
            int nxt = cur ^ 1;
            As[nxt][aK0 + 0][aM] = __uint_as_float(f2tf32(a0r.x));
            As[nxt][aK0 + 1][aM] = __uint_as_float(f2tf32(a0r.y));
            As[nxt][aK0 + 2][aM] = __uint_as_float(f2tf32(a0r.z));
            As[nxt][aK0 + 3][aM] = __uint_as_float(f2tf32(a0r.w));
            As[nxt][aK0 + 4][aM] = __uint_as_float(f2tf32(a1r.x));
            As[nxt][aK0 + 5][aM] = __uint_as_float(f2tf32(a1r.y));
            As[nxt][aK0 + 6][aM] = __uint_as_float(f2tf32(a1r.z));
            As[nxt][aK0 + 7][aM] = __uint_as_float(f2tf32(a1r.w));
            float4 c0 = make_float4(__uint_as_float(f2tf32(b0r.x)), __uint_as_float(f2tf32(b0r.y)),
                                    __uint_as_float(f2tf32(b0r.z)), __uint_as_float(f2tf32(b0r.w)));
            float4 c1 = make_float4(__uint_as_float(f2tf32(b1r.x)), __uint_as_float(f2tf32(b1r.y)),
                                    __uint_as_float(f2tf32(b1r.z)), __uint_as_float(f2tf32(b1r.w)));
            *(float4*)&Bs[nxt][bK][bN0 + 0] = c0;
            *(float4*)&Bs[nxt][bK][bN0 + 4] = c1;
            __syncthreads();
            cur = nxt;
        }
    }

    float* outp = &g_xg[dir][0][0][0];
    #pragma unroll
    for (int nf = 0; nf < 4; nf++) {
        int ncol = nBase + n0w + nf * 8 + 2 * tig;
        float2 bv = *(const float2*)&bias[ncol];
        #pragma unroll
        for (int mf = 0; mf < 4; mf++) {
            int r0 = mBase + m0w + mf * 16 + gid;
            float2 v0 = make_float2(acc[mf][nf][0] + bv.x, acc[mf][nf][1] + bv.y);
            float2 v1 = make_float2(acc[mf][nf][2] + bv.x, acc[mf][nf][3] + bv.y);
            *(float2*)(outp + (size_t)r0 * NG + ncol)       = v0;
            *(float2*)(outp + (size_t)(r0 + 8) * NG + ncol) = v1;
        }
    }
}

// =================================================================================
// Kernel B: persistent bidirectional LSTM recurrence — tf32 tensor cores.
// 64 CTAs (32/dir), 256 threads (8 warps). CTA owns 16 units (= 64 gate-cols):
// halves the per-step h broadcast (4 MB vs 8 MB through L2) and barrier arrivals.
// Warp (khalf = wid>>2, gate = wid&3): tile m32 n16 k256. Split-K pipelined with
// cp.async.cg; R4's proven atomic-epoch barrier; arrive moved before out-stores.
// =================================================================================
#define US_STR 520
#define GP_STR 66
#define SMEM_REC ((96 * US_STR + 2 * 32 * GP_STR) * 4)

__global__ __launch_bounds__(REC_THREADS, 1) void lstm_rec(
    const float* __restrict__ z,
    const float* __restrict__ Uf, const float* __restrict__ Ub,
    float* __restrict__ out)
{
    extern __shared__ float sm[];
    float* Us = sm;                       // [64 local cols][US_STR] (k-permuted tf32)
    float* hs = sm + 64 * US_STR;         // [32 batches][US_STR]   (k-permuted tf32)
    float* gp = sm + 96 * US_STR;         // [2 khalf][32 batches][GP_STR] partial preacts

    const int bid = blockIdx.x;
    const int dir = bid & 1;
    const int blk = bid >> 1;             // 0..31
    const int u0  = blk * UPC;
    const int tid = threadIdx.x;
    const int lane = tid & 31, wid = tid >> 5;
    const int gid = lane >> 2, tig = lane & 3;
    const int khalf = wid >> 2;           // warps 0-3: K<256, warps 4-7: K>=256
    const int wq    = wid & 3;            // this warp's gate (0..3)
    const int lt = tid & 127;             // index within K-half group
    const float* __restrict__ Uw = dir ? Ub : Uf;

    const unsigned ep0 = g_epoch[dir];

    // ---- load U slice into smem: Us[localcol][perm8(k)] (tf32) ----
    // local col ci = gate*16 + unit (0..63); 4 k-chunks of 128
    {
        int ci = tid & 63;
        int kc = tid >> 6;                // 0..3
        int g  = ci >> 4, ul = ci & 15;
        const float* src = Uw + (size_t)(g * U_DIM + u0 + ul);
        float* dst = Us + ci * US_STR;
        for (int k = kc * 128; k < kc * 128 + 128; k++)
            dst[perm8(k)] = __uint_as_float(f2tf32(src[(size_t)k * NG]));
    }

    // ---- init state: h0 = c0 = z; h stored k-PERMUTED + tf32-rounded ----
    float cst[2];
    #pragma unroll
    for (int q = 0; q < 2; q++) {
        int p = tid + q * 256;            // 0..511
        int b = p >> 4, uu = p & 15;
        int ug = u0 + uu;
        int pos = (ug & ~7) | ((ug & 3) << 1) | ((ug & 7) >> 2);
        float zv = z[b * U_DIM + ug];
        cst[q] = zv;
        g_hbuf[dir][0][b][pos] = __uint_as_float(f2tf32(zv));
    }
    __syncthreads();
    if (tid == 0) {
        __threadfence();
        unsigned v = atomicAdd(&g_count[dir], 1u);
        if (v == NCTA_DIR - 1u) {
            g_count[dir] = 0u;
            __threadfence();
            g_epoch[dir] = ep0 + 1u;
        }
    }

    const float* hr0 = hs + gid * US_STR;
    const float* hr1 = hs + (gid + 8) * US_STR;
    const float* hr2 = hs + (gid + 16) * US_STR;
    const float* hr3 = hs + (gid + 24) * US_STR;
    const float* uc0 = Us + (wq * 16 + gid) * US_STR;
    const float* uc1 = Us + (wq * 16 + 8 + gid) * US_STR;
    float* gpb = gp + khalf * 32 * GP_STR;
    const float* xgbase = &g_xg[dir][0][0][0];
    const unsigned hs_s = (unsigned)__cvta_generic_to_shared(hs);

    for (int s = 0; s < T_SEQ; s++) {
        const int buf = s & 1;
        const int tt  = dir ? (T_SEQ - 1 - s) : s;

        // prefetch xg for this step (independent of barrier; hides under spin)
        float xr[2][4];
        #pragma unroll
        for (int q = 0; q < 2; q++) {
            int p = tid + q * 256;
            int b = p >> 4, uu = p & 15;
            const float* xp = xgbase + ((size_t)b * T_SEQ + tt) * NG + u0 + uu;
            xr[q][0] = xp[0];
            xr[q][1] = xp[U_DIM];
            xr[q][2] = xp[2 * U_DIM];
            xr[q][3] = xp[3 * U_DIM];
        }

        // wait for h(s) globally visible
        if (tid == 0) {
            const unsigned target = ep0 + 1u + (unsigned)s;
            while (g_epoch[dir] < target) { }
        }
        __syncthreads();

        // stage this K-half of h into smem: 2 sub-chunks of 128 k, cp.async.cg 16B
        const float* hsrcBase = &g_hbuf[dir][buf][0][0];
        #pragma unroll
        for (int q = 0; q < 2; q++) {
            const int kq = khalf * 256 + q * 128;
            #pragma unroll
            for (int j = 0; j < 8; j++) {
                int idx = j * 128 + lt;           // 0..1023
                int b   = idx >> 5;
                int k   = kq + (idx & 31) * 4;
                const float* src = hsrcBase + b * U_DIM + k;
                unsigned dst = hs_s + (unsigned)(b * US_STR + k) * 4u;
                asm volatile("cp.async.cg.shared.global [%0], [%1], 16;" :: "r"(dst), "l"(src));
            }
            asm volatile("cp.async.commit_group;");
        }

        float cA[4] = {0, 0, 0, 0};   // m-frag0 (b 0..15),  n-frag0
        float cB[4] = {0, 0, 0, 0};   // m-frag0,             n-frag1
        float cC[4] = {0, 0, 0, 0};   // m-frag1 (b 16..31), n-frag0
        float cD[4] = {0, 0, 0, 0};   // m-frag1,             n-frag1

        // sub-chunk 0 ready -> mma kb 0..15 of this half
        asm volatile("cp.async.wait_group 1;");
        asm volatile("bar.sync %0, 128;" :: "r"(1 + khalf));
        #pragma unroll 4
        for (int kb = 0; kb < 16; kb++) {
            int o = khalf * 256 + kb * 8 + 2 * tig;
            uint2 a0 = *(const uint2*)(hr0 + o);
            uint2 a1 = *(const uint2*)(hr1 + o);
            uint2 a2 = *(const uint2*)(hr2 + o);
            uint2 a3 = *(const uint2*)(hr3 + o);
            uint2 b0 = *(const uint2*)(uc0 + o);
            uint2 b1 = *(const uint2*)(uc1 + o);
            mma8(cA, a0.x, a1.x, a0.y, a1.y, b0.x, b0.y);
            mma8(cB, a0.x, a1.x, a0.y, a1.y, b1.x, b1.y);
            mma8(cC, a2.x, a3.x, a2.y, a3.y, b0.x, b0.y);
            mma8(cD, a2.x, a3.x, a2.y, a3.y, b1.x, b1.y);
        }
        // sub-chunk 1 ready -> mma kb 16..31
        asm volatile("cp.async.wait_group 0;");
        asm volatile("bar.sync %0, 128;" :: "r"(1 + khalf));
        #pragma unroll 4
        for (int kb = 16; kb < 32; kb++) {
            int o = khalf * 256 + kb * 8 + 2 * tig;
            uint2 a0 = *(const uint2*)(hr0 + o);
            uint2 a1 = *(const uint2*)(hr1 + o);
            uint2 a2 = *(const uint2*)(hr2 + o);
            uint2 a3 = *(const uint2*)(hr3 + o);
            uint2 b0 = *(const uint2*)(uc0 + o);
            uint2 b1 = *(const uint2*)(uc1 + o);
            mma8(cA, a0.x, a1.x, a0.y, a1.y, b0.x, b0.y);
            mma8(cB, a0.x, a1.x, a0.y, a1.y, b1.x, b1.y);
            mma8(cC, a2.x, a3.x, a2.y, a3.y, b0.x, b0.y);
            mma8(cD, a2.x, a3.x, a2.y, a3.y, b1.x, b1.y);
        }

        // publish partial preactivations (cols = wq*16 + nf*8 + 2tig)
        {
            int c0 = wq * 16 + 2 * tig;
            int c1 = wq * 16 + 8 + 2 * tig;
            *(float2*)&gpb[gid * GP_STR + c0]        = make_float2(cA[0], cA[1]);
            *(float2*)&gpb[(gid + 8) * GP_STR + c0]  = make_float2(cA[2], cA[3]);
            *(float2*)&gpb[gid * GP_STR + c1]        = make_float2(cB[0], cB[1]);
            *(float2*)&gpb[(gid + 8) * GP_STR + c1]  = make_float2(cB[2], cB[3]);
            *(float2*)&gpb[(gid + 16) * GP_STR + c0] = make_float2(cC[0], cC[1]);
            *(float2*)&gpb[(gid + 24) * GP_STR + c0] = make_float2(cC[2], cC[3]);
            *(float2*)&gpb[(gid + 16) * GP_STR + c1] = make_float2(cD[0], cD[1]);
            *(float2*)&gpb[(gid + 24) * GP_STR + c1] = make_float2(cD[2], cD[3]);
        }
        __syncthreads();

        // epilogue: reduce K-halves + xg, gates (i,f,c,o), update, publish h FIRST
        float hv[2];
        #pragma unroll
        for (int q = 0; q < 2; q++) {
            int p = tid + q * 256;
            int b = p >> 4, uu = p & 15;
            const float* p0 = gp + b * GP_STR;
            const float* p1 = gp + (32 + b) * GP_STR;
            float iv = fsigm(xr[q][0] + p0[uu]      + p1[uu]);
            float fv = fsigm(xr[q][1] + p0[16 + uu] + p1[16 + uu]);
            float cc = ftanh(xr[q][2] + p0[32 + uu] + p1[32 + uu]);
            float ov = fsigm(xr[q][3] + p0[48 + uu] + p1[48 + uu]);
            cst[q] = fv * cst[q] + iv * cc;
            hv[q] = ov * ftanh(cst[q]);
            int ug = u0 + uu;
            int pos = (ug & ~7) | ((ug & 3) << 1) | ((ug & 7) >> 2);
            g_hbuf[dir][buf ^ 1][b][pos] = __uint_as_float(f2tf32(hv[q]));
        }
        __syncthreads();

        // arrive: release h(s+1) BEFORE writing outputs (off critical path)
        if (tid == 0) {
            __threadfence();
            unsigned v = atomicAdd(&g_count[dir], 1u);
            if (v == NCTA_DIR - 1u) {
                g_count[dir] = 0u;
                __threadfence();
                g_epoch[dir] = ep0 + 2u + (unsigned)s;
            }
        }

        // output stores
        #pragma unroll
        for (int q = 0; q < 2; q++) {
            int p = tid + q * 256;
            int b = p >> 4, uu = p & 15;
            if (dir == 0)
                out[((size_t)b * T_SEQ + s) * U_DIM + u0 + uu] = hv[q];
            else
                g_hb_out[b][tt][u0 + uu] = hv[q];
        }
    }
}

// =================================================================================
// Kernel C: out += backward outputs
// =================================================================================
__global__ void add_bwd(float* __restrict__ out)
{
    int i = blockIdx.x * blockDim.x + threadIdx.x;
    const int n4 = B_DIM * T_SEQ * U_DIM / 4;
    if (i < n4) {
        float4 a = ((float4*)out)[i];
        float4 b = ((const float4*)&g_hb_out[0][0][0])[i];
        a.x += b.x; a.y += b.y; a.z += b.z; a.w += b.w;
        ((float4*)out)[i] = a;
    }
}

// =================================================================================
extern "C" void kernel_launch(void* const* d_in, const int* in_sizes, int n_in,
                              void* d_out, int out_size)
{
    const float* x  = (const float*)d_in[0];
    const float* z  = (const float*)d_in[1];
    const float* Wf = (const float*)d_in[2];
    const float* Uf = (const float*)d_in[3];
    const float* bf = (const float*)d_in[4];
    const float* Wb = (const float*)d_in[5];
    const float* Ub = (const float*)d_in[6];
    const float* bb = (const float*)d_in[7];
    float* out = (float*)d_out;

    cudaFuncSetAttribute(lstm_rec, cudaFuncAttributeMaxDynamicSharedMemorySize, SMEM_REC);

    dim3 gg(M_TOT / 128, NG / 128, 2);
    gemm_xg<<<gg, 256>>>(x, Wf, bf, Wb, bb);
    lstm_rec<<<2 * NCTA_DIR, REC_THREADS, SMEM_REC>>>(z, Uf, Ub, out);
    add_bwd<<<(B_DIM * T_SEQ * U_DIM / 4 + 255) / 256, 256>>>(out);
}

// round 8
// speedup vs baseline: 1.1288x; 1.0764x over previous
#include <cuda_runtime.h>
#include <math.h>
#include <stdint.h>

#define B_DIM 32
#define T_SEQ 512
#define D_DIM 512
#define U_DIM 512
#define NG    2048                 // 4*U
#define M_TOT (B_DIM * T_SEQ)     // 16384

// ---------------- scratch (static device memory; no allocations) ----------------
__device__ float g_xg[2][B_DIM][T_SEQ][NG];        // input projections, both dirs (256 MB)
__device__ float g_hbuf[2][2][B_DIM][U_DIM];       // h double buffers (k-PERMUTED, tf32-rounded)
__device__ float g_hb_out[B_DIM][T_SEQ][U_DIM];    // backward-direction outputs

// Two-level barrier state: all counters padded to their own 128-B line, monotonic
// across graph replays (mod-8 last-arrival detection; steps are globally ordered
// so each counter receives exactly 8 increments per step window).
__device__ unsigned g_cnt1[2][8][32];              // [dir][group][pad] level-1 counters
__device__ unsigned g_cnt2[2][32];                 // [dir][pad]        root counter
__device__ volatile unsigned g_eporep[2][8][32];   // [dir][group][pad] replicated epoch

#define NCTA_DIR    64
#define REC_THREADS 256

// ---------------- tf32 helpers ----------------
__device__ __forceinline__ unsigned f2tf32(float f)
{
    unsigned r;
    asm("cvt.rna.tf32.f32 %0, %1;" : "=r"(r) : "f"(f));
    return r;
}

// D += A@B, m16n8k8, A row-major, B col-major, tf32 in / fp32 accum
__device__ __forceinline__ void mma8(float* c,
                                     unsigned a0, unsigned a1, unsigned a2, unsigned a3,
                                     unsigned b0, unsigned b1)
{
    asm("mma.sync.aligned.m16n8k8.row.col.f32.tf32.tf32.f32 "
        "{%0,%1,%2,%3},{%4,%5,%6,%7},{%8,%9},{%0,%1,%2,%3};"
        : "+f"(c[0]), "+f"(c[1]), "+f"(c[2]), "+f"(c[3])
        : "r"(a0), "r"(a1), "r"(a2), "r"(a3), "r"(b0), "r"(b1));
}

// k-permutation within each 8-block: (pi(k),pi(k)+1) consecutive = (k, k+4)
__device__ __forceinline__ int perm8(int k)
{
    return (k & ~7) | ((k & 3) << 1) | ((k & 7) >> 2);
}

// ---------------- fast transcendentals (MUFU-based, saturation-safe) ----------------
__device__ __forceinline__ float fsigm(float x)
{
    return __fdividef(1.0f, 1.0f + __expf(-x));        // x->+inf: 1, x->-inf: 0
}
__device__ __forceinline__ float ftanh(float x)
{
    return 1.0f - __fdividef(2.0f, 1.0f + __expf(2.0f * x));  // saturates to +-1
}

// ---------------- two-level tree arrival (called by tid 0 only) ----------------
__device__ __forceinline__ void tree_arrive(int dir, int grp, unsigned ep_next)
{
    __threadfence();
    unsigned v = atomicAdd(&g_cnt1[dir][grp][0], 1u);
    if ((v & 7u) == 7u) {                       // last of this 8-CTA group this step
        unsigned w = atomicAdd(&g_cnt2[dir][0], 1u);
        if ((w & 7u) == 7u) {                   // last group -> publish epoch replicas
            __threadfence();
            #pragma unroll
            for (int g = 0; g < 8; g++)
                g_eporep[dir][g][0] = ep_next;
        }
    }
}

// =================================================================================
// Kernel A: xg[dir] = x @ W[dir] + b[dir]  — tf32 tensor-core GEMM
// 128x128 block tile, BK=16, 256 threads (8 warps, warp tile 64x32).
// Double-buffered smem; 2 CTAs/SM via launch bounds for latency hiding.
// =================================================================================
#define GS 136
__global__ __launch_bounds__(256, 2) void gemm_xg(
    const float* __restrict__ X,
    const float* __restrict__ Wf, const float* __restrict__ bf,
    const float* __restrict__ Wb, const float* __restrict__ bb)
{
    const int dir = blockIdx.z;
    const float* __restrict__ W    = dir ? Wb : Wf;
    const float* __restrict__ bias = dir ? bb : bf;

    __shared__ float As[2][16][GS];   // [buf][k][m]
    __shared__ float Bs[2][16][GS];   // [buf][k][n]

    const int tid   = threadIdx.x;
    const int mBase = blockIdx.x * 128;
    const int nBase = blockIdx.y * 128;
    const int lane  = tid & 31, wid = tid >> 5;
    const int gid   = lane >> 2, tig = lane & 3;
    const int m0w   = (wid & 1) * 64;
    const int n0w   = (wid >> 1) * 32;

    const int aM  = tid >> 1;            // 0..127
    const int aK0 = (tid & 1) * 8;       // 0 or 8
    const int bK  = tid >> 4;            // 0..15
    const int bN0 = (tid & 15) * 8;      // 0..120

    const float* aP = X + (size_t)(mBase + aM) * D_DIM + aK0;
    const float* bP = W + (size_t)bK * NG + nBase + bN0;

    float4 a0r = *(const float4*)aP;
    float4 a1r = *(const float4*)(aP + 4);
    float4 b0r = *(const float4*)bP;
    float4 b1r = *(const float4*)(bP + 4);

    float acc[4][4][4];
    #pragma unroll
    for (int i = 0; i < 4; i++)
        #pragma unroll
        for (int j = 0; j < 4; j++)
            #pragma unroll
            for (int q = 0; q < 4; q++) acc[i][j][q] = 0.0f;

    // prologue: fill buffer 0
    As[0][aK0 + 0][aM] = __uint_as_float(f2tf32(a0r.x));
    As[0][aK0 + 1][aM] = __uint_as_float(f2tf32(a0r.y));
    As[0][aK0 + 2][aM] = __uint_as_float(f2tf32(a0r.z));
    As[0][aK0 + 3][aM] = __uint_as_float(f2tf32(a0r.w));
    As[0][aK0 + 4][aM] = __uint_as_float(f2tf32(a1r.x));
    As[0][aK0 + 5][aM] = __uint_as_float(f2tf32(a1r.y));
    As[0][aK0 + 6][aM] = __uint_as_float(f2tf32(a1r.z));
    As[0][aK0 + 7][aM] = __uint_as_float(f2tf32(a1r.w));
    {
        float4 c0 = make_float4(__uint_as_float(f2tf32(b0r.x)), __uint_as_float(f2tf32(b0r.y)),
                                __uint_as_float(f2tf32(b0r.z)), __uint_as_float(f2tf32(b0r.w)));
        float4 c1 = make_float4(__uint_as_float(f2tf32(b1r.x)), __uint_as_float(f2tf32(b1r.y)),
                                __uint_as_float(f2tf32(b1r.z)), __uint_as_float(f2tf32(b1r.w)));
        *(float4*)&Bs[0][bK][bN0 + 0] = c0;
        *(float4*)&Bs[0][bK][bN0 + 4] = c1;
    }
    __syncthreads();

    int cur = 0;
    for (int kt = 0; kt < D_DIM; kt += 16) {
        const bool more = (kt + 16 < D_DIM);
        if (more) {
            a0r = *(const float4*)(aP + kt + 16);
            a1r = *(const float4*)(aP + kt + 20);
            b0r = *(const float4*)(bP + (size_t)(kt + 16) * NG);
            b1r = *(const float4*)(bP + (size_t)(kt + 16) * NG + 4);
        }

        #pragma unroll
        for (int kk = 0; kk < 16; kk += 8) {
            unsigned af[4][4], bfr[4][2];
            #pragma unroll
            for (int mf = 0; mf < 4; mf++) {
                int mr = m0w + mf * 16 + gid;
                af[mf][0] = __float_as_uint(As[cur][kk + tig][mr]);
                af[mf][1] = __float_as_uint(As[cur][kk + tig][mr + 8]);
                af[mf][2] = __float_as_uint(As[cur][kk + tig + 4][mr]);
                af[mf][3] = __float_as_uint(As[cur][kk + tig + 4][mr + 8]);
            }
            #pragma unroll
            for (int nf = 0; nf < 4; nf++) {
                int nr = n0w + nf * 8 + gid;
                bfr[nf][0] = __float_as_uint(Bs[cur][kk + tig][nr]);
                bfr[nf][1] = __float_as_uint(Bs[cur][kk + tig + 4][nr]);
            }
            #pragma unroll
            for (int mf = 0; mf < 4; mf++)
                #pragma unroll
                for (int nf = 0; nf < 4; nf++)
                    mma8(acc[mf][nf], af[mf][0], af[mf][1], af[mf][2], af[mf][3],
                         bfr[nf][0], bfr[nf][1]);
        }

        if (more) {
            int nxt = cur ^ 1;
            As[nxt][aK0 + 0][aM] = __uint_as_float(f2tf32(a0r.x));
            As[nxt][aK0 + 1][aM] = __uint_as_float(f2tf32(a0r.y));
            As[nxt][aK0 + 2][aM] = __uint_as_float(f2tf32(a0r.z));
            As[nxt][aK0 + 3][aM] = __uint_as_float(f2tf32(a0r.w));
            As[nxt][aK0 + 4][aM] = __uint_as_float(f2tf32(a1r.x));
            As[nxt][aK0 + 5][aM] = __uint_as_float(f2tf32(a1r.y));
            As[nxt][aK0 + 6][aM] = __uint_as_float(f2tf32(a1r.z));
            As[nxt][aK0 + 7][aM] = __uint_as_float(f2tf32(a1r.w));
            float4 c0 = make_float4(__uint_as_float(f2tf32(b0r.x)), __uint_as_float(f2tf32(b0r.y)),
                                    __uint_as_float(f2tf32(b0r.z)), __uint_as_float(f2tf32(b0r.w)));
            float4 c1 = make_float4(__uint_as_float(f2tf32(b1r.x)), __uint_as_float(f2tf32(b1r.y)),
                                    __uint_as_float(f2tf32(b1r.z)), __uint_as_float(f2tf32(b1r.w)));
            *(float4*)&Bs[nxt][bK][bN0 + 0] = c0;
            *(float4*)&Bs[nxt][bK][bN0 + 4] = c1;
            __syncthreads();
            cur = nxt;
        }
    }

    float* outp = &g_xg[dir][0][0][0];
    #pragma unroll
    for (int nf = 0; nf < 4; nf++) {
        int ncol = nBase + n0w + nf * 8 + 2 * tig;
        float2 bv = *(const float2*)&bias[ncol];
        #pragma unroll
        for (int mf = 0; mf < 4; mf++) {
            int r0 = mBase + m0w + mf * 16 + gid;
            float2 v0 = make_float2(acc[mf][nf][0] + bv.x, acc[mf][nf][1] + bv.y);
            float2 v1 = make_float2(acc[mf][nf][2] + bv.x, acc[mf][nf][3] + bv.y);
            *(float2*)(outp + (size_t)r0 * NG + ncol)       = v0;
            *(float2*)(outp + (size_t)(r0 + 8) * NG + ncol) = v1;
        }
    }
}

// =================================================================================
// Kernel B: persistent bidirectional LSTM recurrence — tf32 tensor cores.
// R4 topology (proven fastest): 128 CTAs (64/dir), 256 threads (8 warps), CTA owns
// 8 units (= 32 gate-cols). Split-K pipelined mma with cp.async.cg staging.
// NEW: two-level padded barrier tree + replicated epoch; dir = bid>>6 groups each
// direction's CTAs contiguously; arrive happens BEFORE the output stores.
// =================================================================================
#define US_STR 520
#define GP_STR 34
#define SMEM_REC ((2 * 32 * US_STR + 2 * 32 * GP_STR) * 4)

__global__ __launch_bounds__(REC_THREADS, 1) void lstm_rec(
    const float* __restrict__ z,
    const float* __restrict__ Uf, const float* __restrict__ Ub,
    float* __restrict__ out)
{
    extern __shared__ float sm[];
    float* Us = sm;                       // [32 local cols][US_STR] (k-permuted tf32)
    float* hs = sm + 32 * US_STR;         // [32 batches][US_STR]   (k-permuted tf32)
    float* gp = sm + 64 * US_STR;         // [2 khalf][32 batches][GP_STR] partial preacts

    const int bid = blockIdx.x;
    const int dir = bid >> 6;             // 0..1 (contiguous CTA ranges per direction)
    const int blk = bid & 63;             // 0..63
    const int grp = blk >> 3;             // 0..7 barrier group
    const int u0  = blk * 8;
    const int tid = threadIdx.x;
    const int lane = tid & 31, wid = tid >> 5;
    const int gid = lane >> 2, tig = lane & 3;
    const int mhalf = wid & 1;
    const int gpair = (wid >> 1) & 1;
    const int khalf = wid >> 2;           // threads 0-127: 0, 128-255: 1
    const int g0 = gpair * 2, g1 = g0 + 1;
    const int r0 = mhalf * 16 + gid;
    const int lt = tid & 127;             // index within K-half group
    const float* __restrict__ Uw = dir ? Ub : Uf;

    // epoch base: replicas only advance after ALL CTAs of this dir arrive at the
    // first barrier, which is after this read -> stable across graph replays.
    const unsigned ep0 = g_eporep[dir][grp][0];

    // ---- load U slice into smem: Us[localcol][perm8(k)] (tf32), 256 threads ----
    {
        int ci = tid & 31;                // local col: gate(ci>>3) x unit(ci&7)
        int kc = tid >> 5;                // k chunk (0..7), 64 k each
        int g  = ci >> 3, uul = ci & 7;
        const float* src = Uw + (size_t)(g * U_DIM + u0 + uul);
        float* dst = Us + ci * US_STR;
        for (int k = kc * 64; k < kc * 64 + 64; k++)
            dst[perm8(k)] = __uint_as_float(f2tf32(src[(size_t)k * NG]));
    }

    // ---- init state: h0 = c0 = z; h stored k-PERMUTED + tf32-rounded ----
    float cst;
    {
        int b = tid >> 3, uu = tid & 7;
        float zv = z[b * U_DIM + u0 + uu];
        cst = zv;
        g_hbuf[dir][0][b][u0 + ((uu & 3) << 1) + (uu >> 2)] = __uint_as_float(f2tf32(zv));
    }
    __syncthreads();
    if (tid == 0) tree_arrive(dir, grp, ep0 + 1u);

    const float* hrow0 = hs + r0 * US_STR;
    const float* hrow1 = hs + (r0 + 8) * US_STR;
    const float* urow0 = Us + (g0 * 8 + gid) * US_STR;
    const float* urow1 = Us + (g1 * 8 + gid) * US_STR;
    float* gpb = gp + khalf * 32 * GP_STR;
    const float* xgbase = &g_xg[dir][0][0][0];
    const unsigned hs_s = (unsigned)__cvta_generic_to_shared(hs);
    const int eb = tid >> 3, euu = tid & 7;           // epilogue (batch, unit)

    for (int s = 0; s < T_SEQ; s++) {
        const int buf = s & 1;
        const int tt  = dir ? (T_SEQ - 1 - s) : s;

        // prefetch xg for this step (independent of barrier; hides under spin)
        float xr[4];
        {
            const float* xp = xgbase + ((size_t)eb * T_SEQ + tt) * NG + u0 + euu;
            xr[0] = xp[0];
            xr[1] = xp[U_DIM];
            xr[2] = xp[2 * U_DIM];
            xr[3] = xp[3 * U_DIM];
        }

        // wait for h(s) globally visible: poll this group's epoch replica
        if (tid == 0) {
            const unsigned need = 1u + (unsigned)s;
            while (g_eporep[dir][grp][0] - ep0 < need) { }
        }
        __syncthreads();

        // stage this K-half of h into smem: 2 sub-chunks of 128 k, cp.async.cg 16B
        const float* hsrcBase = &g_hbuf[dir][buf][0][0];
        #pragma unroll
        for (int q = 0; q < 2; q++) {
            const int kq = khalf * 256 + q * 128;
            #pragma unroll
            for (int j = 0; j < 8; j++) {
                int idx = j * 128 + lt;           // 0..1023
                int b   = idx >> 5;
                int k   = kq + (idx & 31) * 4;
                const float* src = hsrcBase + b * U_DIM + k;
                unsigned dst = hs_s + (unsigned)(b * US_STR + k) * 4u;
                asm volatile("cp.async.cg.shared.global [%0], [%1], 16;" :: "r"(dst), "l"(src));
            }
            asm volatile("cp.async.commit_group;");
        }

        float c0f[4] = {0, 0, 0, 0}, c1f[4] = {0, 0, 0, 0};

        // sub-chunk 0 ready -> mma kb 0..15 of this half
        asm volatile("cp.async.wait_group 1;");
        asm volatile("bar.sync %0, 128;" :: "r"(1 + khalf));
        #pragma unroll 4
        for (int kb = 0; kb < 16; kb++) {
            int o = khalf * 256 + kb * 8 + 2 * tig;
            uint2 ar0 = *(const uint2*)(hrow0 + o);
            uint2 ar1 = *(const uint2*)(hrow1 + o);
            uint2 bu0 = *(const uint2*)(urow0 + o);
            uint2 bu1 = *(const uint2*)(urow1 + o);
            mma8(c0f, ar0.x, ar1.x, ar0.y, ar1.y, bu0.x, bu0.y);
            mma8(c1f, ar0.x, ar1.x, ar0.y, ar1.y, bu1.x, bu1.y);
        }
        // sub-chunk 1 ready -> mma kb 16..31
        asm volatile("cp.async.wait_group 0;");
        asm volatile("bar.sync %0, 128;" :: "r"(1 + khalf));
        #pragma unroll 4
        for (int kb = 16; kb < 32; kb++) {
            int o = khalf * 256 + kb * 8 + 2 * tig;
            uint2 ar0 = *(const uint2*)(hrow0 + o);
            uint2 ar1 = *(const uint2*)(hrow1 + o);
            uint2 bu0 = *(const uint2*)(urow0 + o);
            uint2 bu1 = *(const uint2*)(urow1 + o);
            mma8(c0f, ar0.x, ar1.x, ar0.y, ar1.y, bu0.x, bu0.y);
            mma8(c1f, ar0.x, ar1.x, ar0.y, ar1.y, bu1.x, bu1.y);
        }

        // publish partial preactivations
        *(float2*)&gpb[r0 * GP_STR + g0 * 8 + 2 * tig]       = make_float2(c0f[0], c0f[1]);
        *(float2*)&gpb[(r0 + 8) * GP_STR + g0 * 8 + 2 * tig] = make_float2(c0f[2], c0f[3]);
        *(float2*)&gpb[r0 * GP_STR + g1 * 8 + 2 * tig]       = make_float2(c1f[0], c1f[1]);
        *(float2*)&gpb[(r0 + 8) * GP_STR + g1 * 8 + 2 * tig] = make_float2(c1f[2], c1f[3]);
        __syncthreads();

        // epilogue: reduce K-halves + xg, gates (i,f,c,o), update, publish h FIRST
        float hv;
        {
            const float* p0 = gp + eb * GP_STR;
            const float* p1 = gp + (32 + eb) * GP_STR;
            float iv = fsigm(xr[0] + p0[euu]       + p1[euu]);
            float fv = fsigm(xr[1] + p0[8 + euu]   + p1[8 + euu]);
            float cc = ftanh(xr[2] + p0[16 + euu]  + p1[16 + euu]);
            float ov = fsigm(xr[3] + p0[24 + euu]  + p1[24 + euu]);
            cst = fv * cst + iv * cc;
            hv = ov * ftanh(cst);
            g_hbuf[dir][buf ^ 1][eb][u0 + ((euu & 3) << 1) + (euu >> 2)] =
                __uint_as_float(f2tf32(hv));
        }
        __syncthreads();

        // arrive (release h(s+1)) BEFORE output stores — off the critical path
        if (tid == 0) tree_arrive(dir, grp, ep0 + 2u + (unsigned)s);

        if (dir == 0)
            out[((size_t)eb * T_SEQ + s) * U_DIM + u0 + euu] = hv;
        else
            g_hb_out[eb][tt][u0 + euu] = hv;
    }
}

// =================================================================================
// Kernel C: out += backward outputs
// =================================================================================
__global__ void add_bwd(float* __restrict__ out)
{
    int i = blockIdx.x * blockDim.x + threadIdx.x;
    const int n4 = B_DIM * T_SEQ * U_DIM / 4;
    if (i < n4) {
        float4 a = ((float4*)out)[i];
        float4 b = ((const float4*)&g_hb_out[0][0][0])[i];
        a.x += b.x; a.y += b.y; a.z += b.z; a.w += b.w;
        ((float4*)out)[i] = a;
    }
}

// =================================================================================
extern "C" void kernel_launch(void* const* d_in, const int* in_sizes, int n_in,
                              void* d_out, int out_size)
{
    const float* x  = (const float*)d_in[0];
    const float* z  = (const float*)d_in[1];
    const float* Wf = (const float*)d_in[2];
    const float* Uf = (const float*)d_in[3];
    const float* bf = (const float*)d_in[4];
    const float* Wb = (const float*)d_in[5];
    const float* Ub = (const float*)d_in[6];
    const float* bb = (const float*)d_in[7];
    float* out = (float*)d_out;

    cudaFuncSetAttribute(lstm_rec, cudaFuncAttributeMaxDynamicSharedMemorySize, SMEM_REC);

    dim3 gg(M_TOT / 128, NG / 128, 2);
    gemm_xg<<<gg, 256>>>(x, Wf, bf, Wb, bb);
    lstm_rec<<<2 * NCTA_DIR, REC_THREADS, SMEM_REC>>>(z, Uf, Ub, out);
    add_bwd<<<(B_DIM * T_SEQ * U_DIM / 4 + 255) / 256, 256>>>(out);
}

// round 9
// speedup vs baseline: 1.2337x; 1.0929x over previous
#include <cuda_runtime.h>
#include <math.h>
#include <stdint.h>

#define B_DIM 32
#define T_SEQ 512
#define D_DIM 512
#define U_DIM 512
#define NG    2048                 // 4*U
#define M_TOT (B_DIM * T_SEQ)     // 16384

// ---------------- scratch (static device memory; no allocations) ----------------
__device__ float g_xg[2][B_DIM][T_SEQ][NG];        // input projections, both dirs (256 MB)
__device__ float g_hbuf[2][2][B_DIM][U_DIM];       // h double buffers (k-PERMUTED, tf32-rounded)
__device__ float g_hb_out[B_DIM][T_SEQ][U_DIM];    // backward-direction outputs

// Chunked barrier state. chunk c (0..3) of a direction = producer CTAs blk 16c..16c+15,
// covering k-range [128c, 128c+128) of the h broadcast. All words padded to their own
// 128-B line and MONOTONIC across graph replays: each counter gains exactly 16*513 per
// replay (so == 0 mod 16 at every launch) and each epoch word gains exactly 513 (so all
// epoch words are EQUAL at every launch; a CTA reads its own chunk's word pre-arrival,
// which is race-free, and uses it as the base for all chunks).
__device__ unsigned g_chcnt[2][4][32];             // [dir][chunk][pad] arrival counters
__device__ volatile unsigned g_chep[2][4][32];     // [dir][chunk][pad] chunk epochs

#define NCTA_DIR    64
#define REC_THREADS 256

// ---------------- tf32 helpers ----------------
__device__ __forceinline__ unsigned f2tf32(float f)
{
    unsigned r;
    asm("cvt.rna.tf32.f32 %0, %1;" : "=r"(r) : "f"(f));
    return r;
}

// D += A@B, m16n8k8, A row-major, B col-major, tf32 in / fp32 accum
__device__ __forceinline__ void mma8(float* c,
                                     unsigned a0, unsigned a1, unsigned a2, unsigned a3,
                                     unsigned b0, unsigned b1)
{
    asm("mma.sync.aligned.m16n8k8.row.col.f32.tf32.tf32.f32 "
        "{%0,%1,%2,%3},{%4,%5,%6,%7},{%8,%9},{%0,%1,%2,%3};"
        : "+f"(c[0]), "+f"(c[1]), "+f"(c[2]), "+f"(c[3])
        : "r"(a0), "r"(a1), "r"(a2), "r"(a3), "r"(b0), "r"(b1));
}

// k-permutation within each 8-block: (pi(k),pi(k)+1) consecutive = (k, k+4)
__device__ __forceinline__ int perm8(int k)
{
    return (k & ~7) | ((k & 3) << 1) | ((k & 7) >> 2);
}

// ---------------- fast transcendentals (MUFU-based, saturation-safe) ----------------
__device__ __forceinline__ float fsigm(float x)
{
    return __fdividef(1.0f, 1.0f + __expf(-x));        // x->+inf: 1, x->-inf: 0
}
__device__ __forceinline__ float ftanh(float x)
{
    return 1.0f - __fdividef(2.0f, 1.0f + __expf(2.0f * x));  // saturates to +-1
}

// =================================================================================
// Kernel A: xg[dir] = x @ W[dir] + b[dir]  — tf32 tensor-core GEMM
// 128x128 block tile, BK=16, 256 threads (8 warps, warp tile 64x32).
// Double-buffered smem; 2 CTAs/SM via launch bounds for latency hiding.
// =================================================================================
#define GS 136
__global__ __launch_bounds__(256, 2) void gemm_xg(
    const float* __restrict__ X,
    const float* __restrict__ Wf, const float* __restrict__ bf,
    const float* __restrict__ Wb, const float* __restrict__ bb)
{
    const int dir = blockIdx.z;
    const float* __restrict__ W    = dir ? Wb : Wf;
    const float* __restrict__ bias = dir ? bb : bf;

    __shared__ float As[2][16][GS];   // [buf][k][m]
    __shared__ float Bs[2][16][GS];   // [buf][k][n]

    const int tid   = threadIdx.x;
    const int mBase = blockIdx.x * 128;
    const int nBase = blockIdx.y * 128;
    const int lane  = tid & 31, wid = tid >> 5;
    const int gid   = lane >> 2, tig = lane & 3;
    const int m0w   = (wid & 1) * 64;
    const int n0w   = (wid >> 1) * 32;

    const int aM  = tid >> 1;            // 0..127
    const int aK0 = (tid & 1) * 8;       // 0 or 8
    const int bK  = tid >> 4;            // 0..15
    const int bN0 = (tid & 15) * 8;      // 0..120

    const float* aP = X + (size_t)(mBase + aM) * D_DIM + aK0;
    const float* bP = W + (size_t)bK * NG + nBase + bN0;

    float4 a0r = *(const float4*)aP;
    float4 a1r = *(const float4*)(aP + 4);
    float4 b0r = *(const float4*)bP;
    float4 b1r = *(const float4*)(bP + 4);

    float acc[4][4][4];
    #pragma unroll
    for (int i = 0; i < 4; i++)
        #pragma unroll
        for (int j = 0; j < 4; j++)
            #pragma unroll
            for (int q = 0; q < 4; q++) acc[i][j][q] = 0.0f;

    // prologue: fill buffer 0
    As[0][aK0 + 0][aM] = __uint_as_float(f2tf32(a0r.x));
    As[0][aK0 + 1][aM] = __uint_as_float(f2tf32(a0r.y));
    As[0][aK0 + 2][aM] = __uint_as_float(f2tf32(a0r.z));
    As[0][aK0 + 3][aM] = __uint_as_float(f2tf32(a0r.w));
    As[0][aK0 + 4][aM] = __uint_as_float(f2tf32(a1r.x));
    As[0][aK0 + 5][aM] = __uint_as_float(f2tf32(a1r.y));
    As[0][aK0 + 6][aM] = __uint_as_float(f2tf32(a1r.z));
    As[0][aK0 + 7][aM] = __uint_as_float(f2tf32(a1r.w));
    {
        float4 c0 = make_float4(__uint_as_float(f2tf32(b0r.x)), __uint_as_float(f2tf32(b0r.y)),
                                __uint_as_float(f2tf32(b0r.z)), __uint_as_float(f2tf32(b0r.w)));
        float4 c1 = make_float4(__uint_as_float(f2tf32(b1r.x)), __uint_as_float(f2tf32(b1r.y)),
                                __uint_as_float(f2tf32(b1r.z)), __uint_as_float(f2tf32(b1r.w)));
        *(float4*)&Bs[0][bK][bN0 + 0] = c0;
        *(float4*)&Bs[0][bK][bN0 + 4] = c1;
    }
    __syncthreads();

    int cur = 0;
    for (int kt = 0; kt < D_DIM; kt += 16) {
        const bool more = (kt + 16 < D_DIM);
        if (more) {
            a0r = *(const float4*)(aP + kt + 16);
            a1r = *(const float4*)(aP + kt + 20);
            b0r = *(const float4*)(bP + (size_t)(kt + 16) * NG);
            b1r = *(const float4*)(bP + (size_t)(kt + 16) * NG + 4);
        }

        #pragma unroll
        for (int kk = 0; kk < 16; kk += 8) {
            unsigned af[4][4], bfr[4][2];
            #pragma unroll
            for (int mf = 0; mf < 4; mf++) {
                int mr = m0w + mf * 16 + gid;
                af[mf][0] = __float_as_uint(As[cur][kk + tig][mr]);
                af[mf][1] = __float_as_uint(As[cur][kk + tig][mr + 8]);
                af[mf][2] = __float_as_uint(As[cur][kk + tig + 4][mr]);
                af[mf][3] = __float_as_uint(As[cur][kk + tig + 4][mr + 8]);
            }
            #pragma unroll
            for (int nf = 0; nf < 4; nf++) {
                int nr = n0w + nf * 8 + gid;
                bfr[nf][0] = __float_as_uint(Bs[cur][kk + tig][nr]);
                bfr[nf][1] = __float_as_uint(Bs[cur][kk + tig + 4][nr]);
            }
            #pragma unroll
            for (int mf = 0; mf < 4; mf++)
                #pragma unroll
                for (int nf = 0; nf < 4; nf++)
                    mma8(acc[mf][nf], af[mf][0], af[mf][1], af[mf][2], af[mf][3],
                         bfr[nf][0], bfr[nf][1]);
        }

        if (more) {
            int nxt = cur ^ 1;
            As[nxt][aK0 + 0][aM] = __uint_as_float(f2tf32(a0r.x));
            As[nxt][aK0 + 1][aM] = __uint_as_float(f2tf32(a0r.y));
            As[nxt][aK0 + 2][aM] = __uint_as_float(f2tf32(a0r.z));
            As[nxt][aK0 + 3][aM] = __uint_as_float(f2tf32(a0r.w));
            As[nxt][aK0 + 4][aM] = __uint_as_float(f2tf32(a1r.x));
            As[nxt][aK0 + 5][aM] = __uint_as_float(f2tf32(a1r.y));
            As[nxt][aK0 + 6][aM] = __uint_as_float(f2tf32(a1r.z));
            As[nxt][aK0 + 7][aM] = __uint_as_float(f2tf32(a1r.w));
            float4 c0 = make_float4(__uint_as_float(f2tf32(b0r.x)), __uint_as_float(f2tf32(b0r.y)),
                                    __uint_as_float(f2tf32(b0r.z)), __uint_as_float(f2tf32(b0r.w)));
            float4 c1 = make_float4(__uint_as_float(f2tf32(b1r.x)), __uint_as_float(f2tf32(b1r.y)),
                                    __uint_as_float(f2tf32(b1r.z)), __uint_as_float(f2tf32(b1r.w)));
            *(float4*)&Bs[nxt][bK][bN0 + 0] = c0;
            *(float4*)&Bs[nxt][bK][bN0 + 4] = c1;
            __syncthreads();
            cur = nxt;
        }
    }

    float* outp = &g_xg[dir][0][0][0];
    #pragma unroll
    for (int nf = 0; nf < 4; nf++) {
        int ncol = nBase + n0w + nf * 8 + 2 * tig;
        float2 bv = *(const float2*)&bias[ncol];
        #pragma unroll
        for (int mf = 0; mf < 4; mf++) {
            int r0 = mBase + m0w + mf * 16 + gid;
            float2 v0 = make_float2(acc[mf][nf][0] + bv.x, acc[mf][nf][1] + bv.y);
            float2 v1 = make_float2(acc[mf][nf][2] + bv.x, acc[mf][nf][3] + bv.y);
            *(float2*)(outp + (size_t)r0 * NG + ncol)       = v0;
            *(float2*)(outp + (size_t)(r0 + 8) * NG + ncol) = v1;
        }
    }
}

// =================================================================================
// Kernel B: persistent bidirectional LSTM recurrence — tf32 tensor cores.
// R4 topology: 128 CTAs (64/dir, dir=bid&1), 256 threads, CTA owns 8 units.
// Split-K pipelined mma with cp.async.cg staging. NEW: chunk-wise barrier —
// consumers wait per 128-k chunk (16 producer CTAs) instead of for all 64,
// overlapping producer spread with staging + mma of earlier chunks.
// =================================================================================
#define US_STR 520
#define GP_STR 34
#define SMEM_REC ((2 * 32 * US_STR + 2 * 32 * GP_STR) * 4)

__global__ __launch_bounds__(REC_THREADS, 1) void lstm_rec(
    const float* __restrict__ z,
    const float* __restrict__ Uf, const float* __restrict__ Ub,
    float* __restrict__ out)
{
    extern __shared__ float sm[];
    float* Us = sm;                       // [32 local cols][US_STR] (k-permuted tf32)
    float* hs = sm + 32 * US_STR;         // [32 batches][US_STR]   (k-permuted tf32)
    float* gp = sm + 64 * US_STR;         // [2 khalf][32 batches][GP_STR] partial preacts

    const int bid = blockIdx.x;
    const int dir = bid & 1;
    const int blk = bid >> 1;             // 0..63
    const int chunk = blk >> 4;           // 0..3 (this CTA's producer chunk)
    const int u0  = blk * 8;
    const int tid = threadIdx.x;
    const int lane = tid & 31, wid = tid >> 5;
    const int gid = lane >> 2, tig = lane & 3;
    const int mhalf = wid & 1;
    const int gpair = (wid >> 1) & 1;
    const int khalf = wid >> 2;           // threads 0-127: 0, 128-255: 1
    const int g0 = gpair * 2, g1 = g0 + 1;
    const int r0 = mhalf * 16 + gid;
    const int lt = tid & 127;             // index within K-half group
    const float* __restrict__ Uw = dir ? Ub : Uf;

    // Epoch base: read from OUR OWN chunk's word (cannot have been published yet —
    // publishing our chunk requires our own arrival, which is after this read).
    // All chunk words are equal at every replay start, so this base is valid for
    // polling every chunk.
    const unsigned ep0 = g_chep[dir][chunk][0];

    // ---- load U slice into smem: Us[localcol][perm8(k)] (tf32), 256 threads ----
    {
        int ci = tid & 31;                // local col: gate(ci>>3) x unit(ci&7)
        int kc = tid >> 5;                // k chunk (0..7), 64 k each
        int g  = ci >> 3, uul = ci & 7;
        const float* src = Uw + (size_t)(g * U_DIM + u0 + uul);
        float* dst = Us + ci * US_STR;
        for (int k = kc * 64; k < kc * 64 + 64; k++)
            dst[perm8(k)] = __uint_as_float(f2tf32(src[(size_t)k * NG]));
    }

    // ---- init state: h0 = c0 = z; h stored k-PERMUTED + tf32-rounded ----
    float cst;
    {
        int b = tid >> 3, uu = tid & 7;
        float zv = z[b * U_DIM + u0 + uu];
        cst = zv;
        g_hbuf[dir][0][b][u0 + ((uu & 3) << 1) + (uu >> 2)] = __uint_as_float(f2tf32(zv));
    }
    __syncthreads();
    if (tid == 0) {
        __threadfence();
        unsigned v = atomicAdd(&g_chcnt[dir][chunk][0], 1u);
        if ((v & 15u) == 15u) {           // last producer of this chunk this window
            __threadfence();
            g_chep[dir][chunk][0] = ep0 + 1u;
        }
    }

    const float* hrow0 = hs + r0 * US_STR;
    const float* hrow1 = hs + (r0 + 8) * US_STR;
    const float* urow0 = Us + (g0 * 8 + gid) * US_STR;
    const float* urow1 = Us + (g1 * 8 + gid) * US_STR;
    float* gpb = gp + khalf * 32 * GP_STR;
    const float* xgbase = &g_xg[dir][0][0][0];
    const unsigned hs_s = (unsigned)__cvta_generic_to_shared(hs);
    const int eb = tid >> 3, euu = tid & 7;           // epilogue (batch, unit)

    for (int s = 0; s < T_SEQ; s++) {
        const int buf = s & 1;
        const int tt  = dir ? (T_SEQ - 1 - s) : s;

        // prefetch xg for this step (independent of barrier; hides under spin)
        float xr[4];
        {
            const float* xp = xgbase + ((size_t)eb * T_SEQ + tt) * NG + u0 + euu;
            xr[0] = xp[0];
            xr[1] = xp[U_DIM];
            xr[2] = xp[2 * U_DIM];
            xr[3] = xp[3 * U_DIM];
        }

        // chunk-wise: wait for each 128-k chunk's 16 producers, then stage it.
        // khalf 0 consumes chunks 0,1; khalf 1 consumes chunks 2,3.
        const float* hsrcBase = &g_hbuf[dir][buf][0][0];
        #pragma unroll
        for (int q = 0; q < 2; q++) {
            const int ck = khalf * 2 + q;
            if (lt == 0) {
                const unsigned need = 1u + (unsigned)s;
                while (g_chep[dir][ck][0] - ep0 < need) { }
            }
            asm volatile("bar.sync %0, 128;" :: "r"(1 + khalf));
            const int kq = khalf * 256 + q * 128;
            #pragma unroll
            for (int j = 0; j < 8; j++) {
                int idx = j * 128 + lt;           // 0..1023
                int b   = idx >> 5;
                int k   = kq + (idx & 31) * 4;
                const float* src = hsrcBase + b * U_DIM + k;
                unsigned dst = hs_s + (unsigned)(b * US_STR + k) * 4u;
                asm volatile("cp.async.cg.shared.global [%0], [%1], 16;" :: "r"(dst), "l"(src));
            }
            asm volatile("cp.async.commit_group;");
        }

        float c0f[4] = {0, 0, 0, 0}, c1f[4] = {0, 0, 0, 0};

        // sub-chunk 0 ready -> mma kb 0..15 of this half
        asm volatile("cp.async.wait_group 1;");
        asm volatile("bar.sync %0, 128;" :: "r"(1 + khalf));
        #pragma unroll 4
        for (int kb = 0; kb < 16; kb++) {
            int o = khalf * 256 + kb * 8 + 2 * tig;
            uint2 ar0 = *(const uint2*)(hrow0 + o);
            uint2 ar1 = *(const uint2*)(hrow1 + o);
            uint2 bu0 = *(const uint2*)(urow0 + o);
            uint2 bu1 = *(const uint2*)(urow1 + o);
            mma8(c0f, ar0.x, ar1.x, ar0.y, ar1.y, bu0.x, bu0.y);
            mma8(c1f, ar0.x, ar1.x, ar0.y, ar1.y, bu1.x, bu1.y);
        }
        // sub-chunk 1 ready -> mma kb 16..31
        asm volatile("cp.async.wait_group 0;");
        asm volatile("bar.sync %0, 128;" :: "r"(1 + khalf));
        #pragma unroll 4
        for (int kb = 16; kb < 32; kb++) {
            int o = khalf * 256 + kb * 8 + 2 * tig;
            uint2 ar0 = *(const uint2*)(hrow0 + o);
            uint2 ar1 = *(const uint2*)(hrow1 + o);
            uint2 bu0 = *(const uint2*)(urow0 + o);
            uint2 bu1 = *(const uint2*)(urow1 + o);
            mma8(c0f, ar0.x, ar1.x, ar0.y, ar1.y, bu0.x, bu0.y);
            mma8(c1f, ar0.x, ar1.x, ar0.y, ar1.y, bu1.x, bu1.y);
        }

        // publish partial preactivations
        *(float2*)&gpb[r0 * GP_STR + g0 * 8 + 2 * tig]       = make_float2(c0f[0], c0f[1]);
        *(float2*)&gpb[(r0 + 8) * GP_STR + g0 * 8 + 2 * tig] = make_float2(c0f[2], c0f[3]);
        *(float2*)&gpb[r0 * GP_STR + g1 * 8 + 2 * tig]       = make_float2(c1f[0], c1f[1]);
        *(float2*)&gpb[(r0 + 8) * GP_STR + g1 * 8 + 2 * tig] = make_float2(c1f[2], c1f[3]);
        __syncthreads();

        // epilogue: reduce K-halves + xg, gates (i,f,c,o), update, publish h FIRST
        float hv;
        {
            const float* p0 = gp + eb * GP_STR;
            const float* p1 = gp + (32 + eb) * GP_STR;
            float iv = fsigm(xr[0] + p0[euu]       + p1[euu]);
            float fv = fsigm(xr[1] + p0[8 + euu]   + p1[8 + euu]);
            float cc = ftanh(xr[2] + p0[16 + euu]  + p1[16 + euu]);
            float ov = fsigm(xr[3] + p0[24 + euu]  + p1[24 + euu]);
            cst = fv * cst + iv * cc;
            hv = ov * ftanh(cst);
            g_hbuf[dir][buf ^ 1][eb][u0 + ((euu & 3) << 1) + (euu >> 2)] =
                __uint_as_float(f2tf32(hv));
        }
        __syncthreads();

        // arrive (release our slice of h(s+1)) BEFORE output stores
        if (tid == 0) {
            __threadfence();
            unsigned v = atomicAdd(&g_chcnt[dir][chunk][0], 1u);
            if ((v & 15u) == 15u) {
                __threadfence();
                g_chep[dir][chunk][0] = ep0 + 2u + (unsigned)s;
            }
        }

        if (dir == 0)
            out[((size_t)eb * T_SEQ + s) * U_DIM + u0 + euu] = hv;
        else
            g_hb_out[eb][tt][u0 + euu] = hv;
    }
}

// =================================================================================
// Kernel C: out += backward outputs
// =================================================================================
__global__ void add_bwd(float* __restrict__ out)
{
    int i = blockIdx.x * blockDim.x + threadIdx.x;
    const int n4 = B_DIM * T_SEQ * U_DIM / 4;
    if (i < n4) {
        float4 a = ((float4*)out)[i];
        float4 b = ((const float4*)&g_hb_out[0][0][0])[i];
        a.x += b.x; a.y += b.y; a.z += b.z; a.w += b.w;
        ((float4*)out)[i] = a;
    }
}

// =================================================================================
extern "C" void kernel_launch(void* const* d_in, const int* in_sizes, int n_in,
                              void* d_out, int out_size)
{
    const float* x  = (const float*)d_in[0];
    const float* z  = (const float*)d_in[1];
    const float* Wf = (const float*)d_in[2];
    const float* Uf = (const float*)d_in[3];
    const float* bf = (const float*)d_in[4];
    const float* Wb = (const float*)d_in[5];
    const float* Ub = (const float*)d_in[6];
    const float* bb = (const float*)d_in[7];
    float* out = (float*)d_out;

    cudaFuncSetAttribute(lstm_rec, cudaFuncAttributeMaxDynamicSharedMemorySize, SMEM_REC);

    dim3 gg(M_TOT / 128, NG / 128, 2);
    gemm_xg<<<gg, 256>>>(x, Wf, bf, Wb, bb);
    lstm_rec<<<2 * NCTA_DIR, REC_THREADS, SMEM_REC>>>(z, Uf, Ub, out);
    add_bwd<<<(B_DIM * T_SEQ * U_DIM / 4 + 255) / 256, 256>>>(out);
}

// round 10
// speedup vs baseline: 1.2967x; 1.0510x over previous
#include <cuda_runtime.h>
#include <math.h>
#include <stdint.h>

#define B_DIM 32
#define T_SEQ 512
#define D_DIM 512
#define U_DIM 512
#define NG    2048                 // 4*U
#define M_TOT (B_DIM * T_SEQ)     // 16384

// ---------------- scratch (static device memory; no allocations) ----------------
__device__ float g_xg[2][B_DIM][T_SEQ][NG];        // input projections, both dirs (256 MB)
__device__ float g_hbuf[2][2][B_DIM][U_DIM];       // h double buffers (k-PERMUTED, tf32-rounded)
__device__ float g_hb_out[B_DIM][T_SEQ][U_DIM];    // backward-direction outputs
__device__ float g_xT[D_DIM][M_TOT];               // tf32-rounded x, TRANSPOSED [k][m] (32 MB)
__device__ float g_Wc[2][D_DIM][NG];               // tf32-rounded W copies [dir][k][n] (16 MB)

// Chunked barrier state (see R8): chunk c = producer CTAs blk 16c..16c+15 = k-range
// [128c,128c+128). Padded lines, monotonic across graph replays.
__device__ unsigned g_chcnt[2][4][32];             // [dir][chunk][pad] arrival counters
__device__ volatile unsigned g_chep[2][4][32];     // [dir][chunk][pad] chunk epochs

#define NCTA_DIR    64
#define REC_THREADS 256

// ---------------- tf32 helpers ----------------
__device__ __forceinline__ unsigned f2tf32(float f)
{
    unsigned r;
    asm("cvt.rna.tf32.f32 %0, %1;" : "=r"(r) : "f"(f));
    return r;
}

// D += A@B, m16n8k8, A row-major, B col-major, tf32 in / fp32 accum
__device__ __forceinline__ void mma8(float* c,
                                     unsigned a0, unsigned a1, unsigned a2, unsigned a3,
                                     unsigned b0, unsigned b1)
{
    asm("mma.sync.aligned.m16n8k8.row.col.f32.tf32.tf32.f32 "
        "{%0,%1,%2,%3},{%4,%5,%6,%7},{%8,%9},{%0,%1,%2,%3};"
        : "+f"(c[0]), "+f"(c[1]), "+f"(c[2]), "+f"(c[3])
        : "r"(a0), "r"(a1), "r"(a2), "r"(a3), "r"(b0), "r"(b1));
}

// k-permutation within each 8-block: (pi(k),pi(k)+1) consecutive = (k, k+4)
__device__ __forceinline__ int perm8(int k)
{
    return (k & ~7) | ((k & 3) << 1) | ((k & 7) >> 2);
}

// ---------------- fast transcendentals (MUFU-based, saturation-safe) ----------------
__device__ __forceinline__ float fsigm(float x)
{
    return __fdividef(1.0f, 1.0f + __expf(-x));        // x->+inf: 1, x->-inf: 0
}
__device__ __forceinline__ float ftanh(float x)
{
    return 1.0f - __fdividef(2.0f, 1.0f + __expf(2.0f * x));  // saturates to +-1
}

// ---------------- release/acquire barrier primitives (no full MEMBAR) ----------------
__device__ __forceinline__ void ch_arrive(int dir, int chunk, unsigned ep_next)
{
    unsigned v;
    asm volatile("atom.add.release.gpu.u32 %0, [%1], %2;"
                 : "=r"(v)
                 : "l"((unsigned*)&g_chcnt[dir][chunk][0]), "r"(1u)
                 : "memory");
    if ((v & 15u) == 15u)
        asm volatile("st.release.gpu.u32 [%0], %1;"
                     :: "l"((unsigned*)&g_chep[dir][chunk][0]), "r"(ep_next)
                     : "memory");
}

__device__ __forceinline__ void ch_wait(int dir, int ck, unsigned ep0, unsigned need)
{
    unsigned cur;
    do {
        asm volatile("ld.acquire.gpu.u32 %0, [%1];"
                     : "=r"(cur)
                     : "l"((const unsigned*)&g_chep[dir][ck][0])
                     : "memory");
    } while (cur - ep0 < need);
}

// =================================================================================
// Pre-pass 1: x[m][k] -> g_xT[k][m], tf32-rounded (smem tile transpose)
// =================================================================================
__global__ void cvt_xT(const float* __restrict__ X)
{
    __shared__ float t[32][33];
    const int kb = blockIdx.x * 32;
    const int mb = blockIdx.y * 32;
    const int tx = threadIdx.x, ty = threadIdx.y;
    #pragma unroll
    for (int i = ty; i < 32; i += 8)
        t[i][tx] = X[(size_t)(mb + i) * D_DIM + kb + tx];    // t[m'][k'] = X[mb+m'][kb+k']
    __syncthreads();
    #pragma unroll
    for (int i = ty; i < 32; i += 8)
        g_xT[kb + i][mb + tx] = __uint_as_float(f2tf32(t[tx][i]));
}

// =================================================================================
// Pre-pass 2: W[dir][k][n] tf32-rounded straight copy
// =================================================================================
__global__ void cvt_W(const float* __restrict__ Wf, const float* __restrict__ Wb)
{
    const int n4 = D_DIM * NG / 4;                 // per-dir float4 count
    int i = blockIdx.x * blockDim.x + threadIdx.x;
    if (i < 2 * n4) {
        int dir = i >= n4;
        int j = dir ? i - n4 : i;
        float4 v = ((const float4*)(dir ? Wb : Wf))[j];
        v.x = __uint_as_float(f2tf32(v.x));
        v.y = __uint_as_float(f2tf32(v.y));
        v.z = __uint_as_float(f2tf32(v.z));
        v.w = __uint_as_float(f2tf32(v.w));
        ((float4*)&g_Wc[dir][0][0])[j] = v;
    }
}

// =================================================================================
// Kernel A: xg[dir] = xT^T @ Wc[dir] + b[dir]  — tf32 tensor-core GEMM, cp.async.
// 128x128 block tile, BK=16, 256 threads (8 warps, warp tile 64x32).
// 3-stage cp.async.cg ring (pre-converted tf32 inputs: no cvt/STS in mainloop).
// =================================================================================
#define GS 136
#define GSMEM (3 * 16 * GS * 4 * 2)                // As+Bs, 3 buffers = 52,224 B

__global__ __launch_bounds__(256, 2) void gemm_xg(
    const float* __restrict__ bf, const float* __restrict__ bb)
{
    extern __shared__ float gsm[];
    float* As = gsm;                   // [3][16][GS]
    float* Bs = gsm + 3 * 16 * GS;     // [3][16][GS]

    const int dir = blockIdx.z;
    const float* __restrict__ bias = dir ? bb : bf;

    const int tid   = threadIdx.x;
    const int mBase = blockIdx.x * 128;
    const int nBase = blockIdx.y * 128;
    const int lane  = tid & 31, wid = tid >> 5;
    const int gid   = lane >> 2, tig = lane & 3;
    const int m0w   = (wid & 1) * 64;
    const int n0w   = (wid >> 1) * 32;

    const unsigned As_s = (unsigned)__cvta_generic_to_shared(As);
    const unsigned Bs_s = (unsigned)__cvta_generic_to_shared(Bs);
    const float* Wd = &g_Wc[dir][0][0];

    // stage one 16-k tile (A + B) into buffer buf via cp.async.cg (4 chunks/thread)
    auto stage = [&](int buf, int kt) {
        #pragma unroll
        for (int j = 0; j < 2; j++) {
            int ca  = tid + j * 256;               // 0..511
            int row = ca >> 5;                     // 0..15
            int c16 = (ca & 31) * 4;               // 0..124
            const float* srcA = &g_xT[kt + row][mBase + c16];
            const float* srcB = Wd + (size_t)(kt + row) * NG + nBase + c16;
            unsigned dA = As_s + (unsigned)((buf * 16 + row) * GS + c16) * 4u;
            unsigned dB = Bs_s + (unsigned)((buf * 16 + row) * GS + c16) * 4u;
            asm volatile("cp.async.cg.shared.global [%0], [%1], 16;" :: "r"(dA), "l"(srcA));
            asm volatile("cp.async.cg.shared.global [%0], [%1], 16;" :: "r"(dB), "l"(srcB));
        }
        asm volatile("cp.async.commit_group;");
    };

    float acc[4][4][4];
    #pragma unroll
    for (int i = 0; i < 4; i++)
        #pragma unroll
        for (int j = 0; j < 4; j++)
            #pragma unroll
            for (int q = 0; q < 4; q++) acc[i][j][q] = 0.0f;

    stage(0, 0);
    stage(1, 16);

    int cur = 0;
    for (int kt = 0; kt < D_DIM; kt += 16) {
        if (kt + 32 < D_DIM) asm volatile("cp.async.wait_group 1;");
        else                 asm volatile("cp.async.wait_group 0;");
        __syncthreads();
        if (kt + 32 < D_DIM) stage((cur + 2) % 3, kt + 32);

        const float* Ab = As + cur * 16 * GS;
        const float* Bb = Bs + cur * 16 * GS;
        #pragma unroll
        for (int kk = 0; kk < 16; kk += 8) {
            unsigned af[4][4], bfr[4][2];
            #pragma unroll
            for (int mf = 0; mf < 4; mf++) {
                int mr = m0w + mf * 16 + gid;
                af[mf][0] = __float_as_uint(Ab[(kk + tig) * GS + mr]);
                af[mf][1] = __float_as_uint(Ab[(kk + tig) * GS + mr + 8]);
                af[mf][2] = __float_as_uint(Ab[(kk + tig + 4) * GS + mr]);
                af[mf][3] = __float_as_uint(Ab[(kk + tig + 4) * GS + mr + 8]);
            }
            #pragma unroll
            for (int nf = 0; nf < 4; nf++) {
                int nr = n0w + nf * 8 + gid;
                bfr[nf][0] = __float_as_uint(Bb[(kk + tig) * GS + nr]);
                bfr[nf][1] = __float_as_uint(Bb[(kk + tig + 4) * GS + nr]);
            }
            #pragma unroll
            for (int mf = 0; mf < 4; mf++)
                #pragma unroll
                for (int nf = 0; nf < 4; nf++)
                    mma8(acc[mf][nf], af[mf][0], af[mf][1], af[mf][2], af[mf][3],
                         bfr[nf][0], bfr[nf][1]);
        }
        cur = (cur + 1) % 3;
    }

    float* outp = &g_xg[dir][0][0][0];
    #pragma unroll
    for (int nf = 0; nf < 4; nf++) {
        int ncol = nBase + n0w + nf * 8 + 2 * tig;
        float2 bv = *(const float2*)&bias[ncol];
        #pragma unroll
        for (int mf = 0; mf < 4; mf++) {
            int r0 = mBase + m0w + mf * 16 + gid;
            float2 v0 = make_float2(acc[mf][nf][0] + bv.x, acc[mf][nf][1] + bv.y);
            float2 v1 = make_float2(acc[mf][nf][2] + bv.x, acc[mf][nf][3] + bv.y);
            *(float2*)(outp + (size_t)r0 * NG + ncol)       = v0;
            *(float2*)(outp + (size_t)(r0 + 8) * NG + ncol) = v1;
        }
    }
}

// =================================================================================
// Kernel B: persistent bidirectional LSTM recurrence — tf32 tensor cores.
// R8 structure (proven): 128 CTAs (64/dir, dir=bid&1), 256 threads, CTA owns 8
// units; split-K pipelined mma + cp.async.cg; chunk-wise barrier, now with
// release/acquire atomics instead of full MEMBAR fences.
// =================================================================================
#define US_STR 520
#define GP_STR 34
#define SMEM_REC ((2 * 32 * US_STR + 2 * 32 * GP_STR) * 4)

__global__ __launch_bounds__(REC_THREADS, 1) void lstm_rec(
    const float* __restrict__ z,
    const float* __restrict__ Uf, const float* __restrict__ Ub,
    float* __restrict__ out)
{
    extern __shared__ float sm[];
    float* Us = sm;                       // [32 local cols][US_STR] (k-permuted tf32)
    float* hs = sm + 32 * US_STR;         // [32 batches][US_STR]   (k-permuted tf32)
    float* gp = sm + 64 * US_STR;         // [2 khalf][32 batches][GP_STR] partial preacts

    const int bid = blockIdx.x;
    const int dir = bid & 1;
    const int blk = bid >> 1;             // 0..63
    const int chunk = blk >> 4;           // 0..3 (this CTA's producer chunk)
    const int u0  = blk * 8;
    const int tid = threadIdx.x;
    const int lane = tid & 31, wid = tid >> 5;
    const int gid = lane >> 2, tig = lane & 3;
    const int mhalf = wid & 1;
    const int gpair = (wid >> 1) & 1;
    const int khalf = wid >> 2;           // threads 0-127: 0, 128-255: 1
    const int g0 = gpair * 2, g1 = g0 + 1;
    const int r0 = mhalf * 16 + gid;
    const int lt = tid & 127;             // index within K-half group
    const float* __restrict__ Uw = dir ? Ub : Uf;

    // Epoch base: own chunk's word (race-free pre-arrival read; all words equal
    // at every replay start).
    const unsigned ep0 = g_chep[dir][chunk][0];

    // ---- load U slice into smem: Us[localcol][perm8(k)] (tf32), 256 threads ----
    {
        int ci = tid & 31;                // local col: gate(ci>>3) x unit(ci&7)
        int kc = tid >> 5;                // k chunk (0..7), 64 k each
        int g  = ci >> 3, uul = ci & 7;
        const float* src = Uw + (size_t)(g * U_DIM + u0 + uul);
        float* dst = Us + ci * US_STR;
        for (int k = kc * 64; k < kc * 64 + 64; k++)
            dst[perm8(k)] = __uint_as_float(f2tf32(src[(size_t)k * NG]));
    }

    // ---- init state: h0 = c0 = z; h stored k-PERMUTED + tf32-rounded ----
    float cst;
    {
        int b = tid >> 3, uu = tid & 7;
        float zv = z[b * U_DIM + u0 + uu];
        cst = zv;
        g_hbuf[dir][0][b][u0 + ((uu & 3) << 1) + (uu >> 2)] = __uint_as_float(f2tf32(zv));
    }
    __syncthreads();
    if (tid == 0) ch_arrive(dir, chunk, ep0 + 1u);

    const float* hrow0 = hs + r0 * US_STR;
    const float* hrow1 = hs + (r0 + 8) * US_STR;
    const float* urow0 = Us + (g0 * 8 + gid) * US_STR;
    const float* urow1 = Us + (g1 * 8 + gid) * US_STR;
    float* gpb = gp + khalf * 32 * GP_STR;
    const float* xgbase = &g_xg[dir][0][0][0];
    const unsigned hs_s = (unsigned)__cvta_generic_to_shared(hs);
    const int eb = tid >> 3, euu = tid & 7;           // epilogue (batch, unit)

    for (int s = 0; s < T_SEQ; s++) {
        const int buf = s & 1;
        const int tt  = dir ? (T_SEQ - 1 - s) : s;

        // prefetch xg for this step (independent of barrier; hides under spin)
        float xr[4];
        {
            const float* xp = xgbase + ((size_t)eb * T_SEQ + tt) * NG + u0 + euu;
            xr[0] = xp[0];
            xr[1] = xp[U_DIM];
            xr[2] = xp[2 * U_DIM];
            xr[3] = xp[3 * U_DIM];
        }

        // chunk-wise: wait for each 128-k chunk's 16 producers, then stage it.
        // khalf 0 consumes chunks 0,1; khalf 1 consumes chunks 2,3.
        const float* hsrcBase = &g_hbuf[dir][buf][0][0];
        #pragma unroll
        for (int q = 0; q < 2; q++) {
            const int ck = khalf * 2 + q;
            if (lt == 0) ch_wait(dir, ck, ep0, 1u + (unsigned)s);
            asm volatile("bar.sync %0, 128;" :: "r"(1 + khalf));
            const int kq = khalf * 256 + q * 128;
            #pragma unroll
            for (int j = 0; j < 8; j++) {
                int idx = j * 128 + lt;           // 0..1023
                int b   = idx >> 5;
                int k   = kq + (idx & 31) * 4;
                const float* src = hsrcBase + b * U_DIM + k;
                unsigned dst = hs_s + (unsigned)(b * US_STR + k) * 4u;
                asm volatile("cp.async.cg.shared.global [%0], [%1], 16;" :: "r"(dst), "l"(src));
            }
            asm volatile("cp.async.commit_group;");
        }

        float c0f[4] = {0, 0, 0, 0}, c1f[4] = {0, 0, 0, 0};

        // sub-chunk 0 ready -> mma kb 0..15 of this half
        asm volatile("cp.async.wait_group 1;");
        asm volatile("bar.sync %0, 128;" :: "r"(1 + khalf));
        #pragma unroll 4
        for (int kb = 0; kb < 16; kb++) {
            int o = khalf * 256 + kb * 8 + 2 * tig;
            uint2 ar0 = *(const uint2*)(hrow0 + o);
            uint2 ar1 = *(const uint2*)(hrow1 + o);
            uint2 bu0 = *(const uint2*)(urow0 + o);
            uint2 bu1 = *(const uint2*)(urow1 + o);
            mma8(c0f, ar0.x, ar1.x, ar0.y, ar1.y, bu0.x, bu0.y);
            mma8(c1f, ar0.x, ar1.x, ar0.y, ar1.y, bu1.x, bu1.y);
        }
        // sub-chunk 1 ready -> mma kb 16..31
        asm volatile("cp.async.wait_group 0;");
        asm volatile("bar.sync %0, 128;" :: "r"(1 + khalf));
        #pragma unroll 4
        for (int kb = 16; kb < 32; kb++) {
            int o = khalf * 256 + kb * 8 + 2 * tig;
            uint2 ar0 = *(const uint2*)(hrow0 + o);
            uint2 ar1 = *(const uint2*)(hrow1 + o);
            uint2 bu0 = *(const uint2*)(urow0 + o);
            uint2 bu1 = *(const uint2*)(urow1 + o);
            mma8(c0f, ar0.x, ar1.x, ar0.y, ar1.y, bu0.x, bu0.y);
            mma8(c1f, ar0.x, ar1.x, ar0.y, ar1.y, bu1.x, bu1.y);
        }

        // publish partial preactivations
        *(float2*)&gpb[r0 * GP_STR + g0 * 8 + 2 * tig]       = make_float2(c0f[0], c0f[1]);
        *(float2*)&gpb[(r0 + 8) * GP_STR + g0 * 8 + 2 * tig] = make_float2(c0f[2], c0f[3]);
        *(float2*)&gpb[r0 * GP_STR + g1 * 8 + 2 * tig]       = make_float2(c1f[0], c1f[1]);
        *(float2*)&gpb[(r0 + 8) * GP_STR + g1 * 8 + 2 * tig] = make_float2(c1f[2], c1f[3]);
        __syncthreads();

        // epilogue: reduce K-halves + xg, gates (i,f,c,o), update, publish h FIRST
        float hv;
        {
            const float* p0 = gp + eb * GP_STR;
            const float* p1 = gp + (32 + eb) * GP_STR;
            float iv = fsigm(xr[0] + p0[euu]       + p1[euu]);
            float fv = fsigm(xr[1] + p0[8 + euu]   + p1[8 + euu]);
            float cc = ftanh(xr[2] + p0[16 + euu]  + p1[16 + euu]);
            float ov = fsigm(xr[3] + p0[24 + euu]  + p1[24 + euu]);
            cst = fv * cst + iv * cc;
            hv = ov * ftanh(cst);
            g_hbuf[dir][buf ^ 1][eb][u0 + ((euu & 3) << 1) + (euu >> 2)] =
                __uint_as_float(f2tf32(hv));
        }
        __syncthreads();

        // arrive (release our slice of h(s+1)) BEFORE output stores
        if (tid == 0) ch_arrive(dir, chunk, ep0 + 2u + (unsigned)s);

        if (dir == 0)
            out[((size_t)eb * T_SEQ + s) * U_DIM + u0 + euu] = hv;
        else
            g_hb_out[eb][tt][u0 + euu] = hv;
    }
}

// =================================================================================
// Kernel C: out += backward outputs
// =================================================================================
__global__ void add_bwd(float* __restrict__ out)
{
    int i = blockIdx.x * blockDim.x + threadIdx.x;
    const int n4 = B_DIM * T_SEQ * U_DIM / 4;
    if (i < n4) {
        float4 a = ((float4*)out)[i];
        float4 b = ((const float4*)&g_hb_out[0][0][0])[i];
        a.x += b.x; a.y += b.y; a.z += b.z; a.w += b.w;
        ((float4*)out)[i] = a;
    }
}

// =================================================================================
extern "C" void kernel_launch(void* const* d_in, const int* in_sizes, int n_in,
                              void* d_out, int out_size)
{
    const float* x  = (const float*)d_in[0];
    const float* z  = (const float*)d_in[1];
    const float* Wf = (const float*)d_in[2];
    const float* Uf = (const float*)d_in[3];
    const float* bf = (const float*)d_in[4];
    const float* Wb = (const float*)d_in[5];
    const float* Ub = (const float*)d_in[6];
    const float* bb = (const float*)d_in[7];
    float* out = (float*)d_out;

    cudaFuncSetAttribute(gemm_xg, cudaFuncAttributeMaxDynamicSharedMemorySize, GSMEM);
    cudaFuncSetAttribute(lstm_rec, cudaFuncAttributeMaxDynamicSharedMemorySize, SMEM_REC);

    // pre-passes: tf32-rounded x (transposed) and W copies
    cvt_xT<<<dim3(D_DIM / 32, M_TOT / 32), dim3(32, 8)>>>(x);
    {
        int total4 = 2 * D_DIM * NG / 4;
        cvt_W<<<(total4 + 255) / 256, 256>>>(Wf, Wb);
    }

    dim3 gg(M_TOT / 128, NG / 128, 2);
    gemm_xg<<<gg, 256, GSMEM>>>(bf, bb);
    lstm_rec<<<2 * NCTA_DIR, REC_THREADS, SMEM_REC>>>(z, Uf, Ub, out);
    add_bwd<<<(B_DIM * T_SEQ * U_DIM / 4 + 255) / 256, 256>>>(out);
}